// round 3
// baseline (speedup 1.0000x reference)
#include <cuda_runtime.h>
#include <math.h>

#define BB 512
#define NW_ 256
#define NS_ 8
#define PP 32
#define DD 512
#define HH 16
#define QKD 32
#define AA 34
#define INV_NORM (1.0f/300.0f)

// ---------------- scratch (static device globals; no allocation) ----------------
__device__ __align__(128) float g_X1[(size_t)BB*PP*3*DD];        // (16384, 1536)
__device__ __align__(128) float g_pm_emb[(size_t)BB*PP*DD];      // (16384, 512)
__device__ __align__(128) float g_action[(size_t)BB*AA*3*DD];    // (17408, 1536)
__device__ __align__(128) float g_K[(size_t)BB*AA*DD];
__device__ __align__(128) float g_V[(size_t)BB*AA*DD];
__device__ __align__(128) float g_SHK[(size_t)BB*AA*DD];
__device__ __align__(128) float g_g12[(size_t)BB*2*DD];
__device__ __align__(128) float g_pmmean[(size_t)BB*DD];
__device__ __align__(128) float g_pmrb[(size_t)BB*DD];
__device__ __align__(128) float g_ctx[(size_t)BB*3*DD];
__device__ __align__(128) float g_h1[(size_t)BB*DD];
__device__ __align__(128) float g_ctxt[(size_t)BB*DD];
__device__ __align__(128) float g_q[(size_t)BB*DD];
__device__ __align__(128) float g_attout[(size_t)BB*DD];
__device__ __align__(128) float g_mh[(size_t)BB*DD];
__device__ __align__(128) float g_dll[BB];
__device__ __align__(128) float g_dpm[BB*PP];
__device__ int g_mask_wordmode;   // 1: mask indexed as 32-bit words (int32/float32), 0: bytes

// ---------------- mask dtype sniffer -------------------------------------------
// Reads exactly 17408 bytes (= BB*AA bytes = BB*AA/4 words), safe for uint8,
// int32 or float32 storage of the (BB, AA) bool mask.
__global__ void detect_mask(const unsigned int* __restrict__ mw)
{
    __shared__ int bad;
    if (threadIdx.x == 0) bad = 0;
    __syncthreads();
    for (int i = threadIdx.x; i < (BB * AA) / 4; i += blockDim.x) {
        unsigned int w = mw[i];
        if (w != 0u && w != 1u && w != 0x3F800000u) atomicExch(&bad, 1);
    }
    __syncthreads();
    if (threadIdx.x == 0) g_mask_wordmode = !bad;
}

__device__ __forceinline__ bool mask_at(const void* m, int i)
{
    if (g_mask_wordmode) return ((const unsigned int*)m)[i] != 0u;
    return ((const unsigned char*)m)[i] != 0u;
}

// ---------------- NT SGEMM: C[M,N] = A[M,K] * B[N,K]^T (+bias, +relu) ----------
// Requires: M%128==0, N%128==0, K%8==0. 128x128x8 tile, 256 thr, 8x8/thread.
template<bool RELU>
__global__ void __launch_bounds__(256) sgemm_nt(
    const float* __restrict__ A, const float* __restrict__ Bm,
    float* __restrict__ C, int M, int N, int K,
    int ldc, int n0, const float* __restrict__ bias)
{
    __shared__ float As[8][128];
    __shared__ float Bs[8][128];
    const int tid = threadIdx.x;
    const int bm = blockIdx.y * 128;
    const int bn = blockIdx.x * 128;
    const int tx = tid & 15;
    const int ty = tid >> 4;
    const int lr = tid >> 1;         // 0..127
    const int lc = (tid & 1) * 4;    // 0 or 4

    float acc[8][8];
    #pragma unroll
    for (int i = 0; i < 8; i++)
        #pragma unroll
        for (int j = 0; j < 8; j++) acc[i][j] = 0.f;

    const float* Aptr = A + (size_t)(bm + lr) * K + lc;
    const float* Bptr = Bm + (size_t)(bn + lr) * K + lc;

    for (int k0 = 0; k0 < K; k0 += 8) {
        float4 av = *(const float4*)(Aptr + k0);
        float4 bv = *(const float4*)(Bptr + k0);
        __syncthreads();
        As[lc + 0][lr] = av.x; As[lc + 1][lr] = av.y;
        As[lc + 2][lr] = av.z; As[lc + 3][lr] = av.w;
        Bs[lc + 0][lr] = bv.x; Bs[lc + 1][lr] = bv.y;
        Bs[lc + 2][lr] = bv.z; Bs[lc + 3][lr] = bv.w;
        __syncthreads();
        #pragma unroll
        for (int kk = 0; kk < 8; kk++) {
            float a[8], b[8];
            *(float4*)(a)     = *(const float4*)&As[kk][ty * 8];
            *(float4*)(a + 4) = *(const float4*)&As[kk][ty * 8 + 4];
            *(float4*)(b)     = *(const float4*)&Bs[kk][tx * 8];
            *(float4*)(b + 4) = *(const float4*)&Bs[kk][tx * 8 + 4];
            #pragma unroll
            for (int i = 0; i < 8; i++)
                #pragma unroll
                for (int j = 0; j < 8; j++)
                    acc[i][j] = fmaf(a[i], b[j], acc[i][j]);
        }
    }

    #pragma unroll
    for (int i = 0; i < 8; i++) {
        int row = bm + ty * 8 + i;
        #pragma unroll
        for (int j = 0; j < 8; j++) {
            int col = bn + tx * 8 + j;
            float v = acc[i][j];
            if (bias) v += bias[col];
            if (RELU) v = fmaxf(v, 0.f);
            C[(size_t)row * ldc + n0 + col] = v;
        }
    }
}

// ---------------- build X1 = [pm_stage | pm_wafer | remain*W_dyn[:,0]] ----------
__global__ void build_x1(const float* __restrict__ enc_row, const float* __restrict__ enc_col,
                         const float* __restrict__ clockv, const float* __restrict__ endt,
                         const int* __restrict__ loc_id, const int* __restrict__ robot,
                         const int* __restrict__ hold, const int* __restrict__ stage,
                         const float* __restrict__ Wdyn)
{
    int blk = blockIdx.x;                // b*32 + p
    int b = blk >> 5, p = blk & 31;
    float ck = clockv[b];
    float et = endt[b * PP + p];
    float remain = fmaxf(et - ck, 0.f) * INV_NORM;
    int st = stage[b * PP + p] - 1;
    int hw = hold[b * PP + p];
    float* row = g_X1 + (size_t)blk * (3 * DD);
    const float* cs = enc_col + ((size_t)b * NS_ + st) * DD;
    const float* ws = (hw >= 0) ? enc_row + ((size_t)b * NW_ + hw) * DD : nullptr;
    for (int d = threadIdx.x; d < DD; d += blockDim.x) {
        row[d] = cs[d];
        row[DD + d] = ws ? ws[d] : 0.f;
        row[2 * DD + d] = remain * Wdyn[2 * d];
    }
    if (threadIdx.x == 0) {
        int rb = robot[b];
        float pk = ck + 3.f * (loc_id[b * PP + p] != rb);
        g_dpm[blk] = (fmaxf(et, pk) + 9.f - ck) * INV_NORM;
        if (p == 0) g_dll[b] = (3.f * (rb != 0) + 9.f) * INV_NORM;
    }
}

__global__ void build_g12(const float* __restrict__ enc_row,
                          const int* __restrict__ ll1, const int* __restrict__ ll2)
{
    int b = blockIdx.x;
    const float* r1 = enc_row + ((size_t)b * NW_ + ll1[b]) * DD;
    const float* r2 = enc_row + ((size_t)b * NW_ + ll2[b]) * DD;
    float* dst = g_g12 + (size_t)b * 2 * DD;
    for (int d = threadIdx.x; d < DD; d += blockDim.x) {
        dst[d] = r1[d];
        dst[DD + d] = r2[d];
    }
}

// ---------------- build action (B, 34, 3D) ----------------
__global__ void build_action(const float* __restrict__ enc_row,
                             const int* __restrict__ ll1, const int* __restrict__ ll2,
                             const int* __restrict__ hold, const float* __restrict__ Wtime)
{
    int blk = blockIdx.x;                // b*34 + j
    int b = blk / AA, j = blk % AA;
    float* row = g_action + (size_t)blk * (3 * DD);
    if (j < 2) {
        int rec = (j == 0) ? ll1[b] : ll2[b];
        const float* g = enc_row + ((size_t)b * NW_ + rec) * DD;
        float dl = g_dll[b];
        for (int d = threadIdx.x; d < DD; d += blockDim.x) {
            row[d] = 0.f;
            row[DD + d] = g[d];
            row[2 * DD + d] = dl * Wtime[d];
        }
    } else {
        int p = j - 2;
        int hw = hold[b * PP + p];
        const float* ws = (hw >= 0) ? enc_row + ((size_t)b * NW_ + hw) * DD : nullptr;
        const float* pe = g_pm_emb + (size_t)(b * PP + p) * DD;
        float dp = g_dpm[b * PP + p];
        for (int d = threadIdx.x; d < DD; d += blockDim.x) {
            row[d] = pe[d];
            row[DD + d] = ws ? ws[d] : 0.f;
            row[2 * DD + d] = dp * Wtime[d];
        }
    }
}

// ---------------- pm_emb mean over P and robot-loc gather ----------------
__global__ void pm_mean_rb(const int* __restrict__ robot)
{
    int b = blockIdx.x;
    int rb = robot[b];
    for (int d = threadIdx.x; d < DD; d += blockDim.x) {
        float s = 0.f;
        #pragma unroll 8
        for (int p = 0; p < PP; p++)
            s += g_pm_emb[((size_t)(b * PP + p)) * DD + d];
        g_pmmean[(size_t)b * DD + d] = s * (1.f / PP);
        g_pmrb[(size_t)b * DD + d] = g_pm_emb[((size_t)(b * PP + rb)) * DD + d];
    }
}

// ---------------- attention: 16 heads x (1 x 34) per batch ----------------
__global__ void attention(const void* __restrict__ mask)
{
    int b = blockIdx.x;
    int h = threadIdx.x >> 5, lane = threadIdx.x & 31;
    __shared__ float ps[HH][AA + 2];
    float q = g_q[(size_t)b * DD + h * QKD + lane];
    const float scale = rsqrtf((float)QKD);
    for (int j = 0; j < AA; j++) {
        float kv = g_K[((size_t)(b * AA + j)) * DD + h * QKD + lane];
        float s = q * kv;
        #pragma unroll
        for (int o = 16; o > 0; o >>= 1) s += __shfl_xor_sync(0xffffffffu, s, o);
        if (lane == 0) ps[h][j] = s * scale + (mask_at(mask, b * AA + j) ? 0.f : -1e10f);
    }
    __syncwarp();
    float m = -INFINITY;
    for (int j = 0; j < AA; j++) m = fmaxf(m, ps[h][j]);
    float sum = 0.f;
    for (int j = 0; j < AA; j++) sum += expf(ps[h][j] - m);
    float inv = 1.f / sum;
    float o = 0.f;
    for (int j = 0; j < AA; j++)
        o += expf(ps[h][j] - m) * inv * g_V[((size_t)(b * AA + j)) * DD + h * QKD + lane];
    g_attout[(size_t)b * DD + h * QKD + lane] = o;
}

// ---------------- final: sc = 10*tanh(mh . shk / sqrt(D)) + ninf ; softmax ------
__global__ void final_kernel(const void* __restrict__ mask, float* __restrict__ out)
{
    int b = blockIdx.x;
    int w = threadIdx.x >> 5, lane = threadIdx.x & 31;  // 8 warps
    __shared__ float sc[AA];
    const float* mh = g_mh + (size_t)b * DD;
    const float scale = rsqrtf((float)DD);
    for (int a = w; a < AA; a += 8) {
        const float* s = g_SHK + ((size_t)(b * AA + a)) * DD;
        float acc = 0.f;
        for (int d = lane; d < DD; d += 32) acc = fmaf(mh[d], s[d], acc);
        #pragma unroll
        for (int o = 16; o > 0; o >>= 1) acc += __shfl_xor_sync(0xffffffffu, acc, o);
        if (lane == 0)
            sc[a] = 10.f * tanhf(acc * scale) + (mask_at(mask, b * AA + a) ? 0.f : -1e10f);
    }
    __syncthreads();
    if (threadIdx.x < AA) {
        float m = -INFINITY;
        for (int j = 0; j < AA; j++) m = fmaxf(m, sc[j]);
        float sum = 0.f;
        for (int j = 0; j < AA; j++) sum += expf(sc[j] - m);
        out[b * AA + threadIdx.x] = expf(sc[threadIdx.x] - m) / sum;
    }
}

// ---------------- launch ----------------
static inline void gemm(const float* A, const float* Bm, float* C,
                        int M, int N, int K, int ldc, int n0,
                        const float* bias, bool relu)
{
    dim3 grid(N / 128, M / 128);
    if (relu) sgemm_nt<true><<<grid, 256>>>(A, Bm, C, M, N, K, ldc, n0, bias);
    else      sgemm_nt<false><<<grid, 256>>>(A, Bm, C, M, N, K, ldc, n0, bias);
}

extern "C" void kernel_launch(void* const* d_in, const int* in_sizes, int n_in,
                              void* d_out, int out_size)
{
    const float* enc_row = (const float*)d_in[0];
    const float* enc_col = (const float*)d_in[1];
    const float* clockv  = (const float*)d_in[2];
    const float* endt    = (const float*)d_in[3];
    const int* loc_id    = (const int*)d_in[4];
    const int* robot     = (const int*)d_in[5];
    const int* hold      = (const int*)d_in[6];
    const int* stage     = (const int*)d_in[7];
    const int* ll1       = (const int*)d_in[8];
    const int* ll2       = (const int*)d_in[9];
    const void* mask     = d_in[10];
    const float* W_dyn   = (const float*)d_in[11];
    const float* W_pmcat = (const float*)d_in[12];
    const float* W_time  = (const float*)d_in[13];
    const float* W_llctx = (const float*)d_in[14];
    const float* W_pmctx = (const float*)d_in[15];
    const float* W_rbctx = (const float*)d_in[16];
    const float* W_cc1   = (const float*)d_in[17];
    const float* b_cc1   = (const float*)d_in[18];
    const float* W_cc2   = (const float*)d_in[19];
    const float* b_cc2   = (const float*)d_in[20];
    const float* Wq      = (const float*)d_in[21];
    const float* Wk      = (const float*)d_in[22];
    const float* Wv      = (const float*)d_in[23];
    const float* Wshk    = (const float*)d_in[24];
    const float* W_mhc   = (const float*)d_in[25];
    const float* b_mhc   = (const float*)d_in[26];
    float* out = (float*)d_out;

    float *X1, *pm_emb, *action, *Km, *Vm, *SHK, *g12, *pmmean, *pmrb, *ctx, *h1, *ctxt, *qm, *attout, *mh;
    cudaGetSymbolAddress((void**)&X1, g_X1);
    cudaGetSymbolAddress((void**)&pm_emb, g_pm_emb);
    cudaGetSymbolAddress((void**)&action, g_action);
    cudaGetSymbolAddress((void**)&Km, g_K);
    cudaGetSymbolAddress((void**)&Vm, g_V);
    cudaGetSymbolAddress((void**)&SHK, g_SHK);
    cudaGetSymbolAddress((void**)&g12, g_g12);
    cudaGetSymbolAddress((void**)&pmmean, g_pmmean);
    cudaGetSymbolAddress((void**)&pmrb, g_pmrb);
    cudaGetSymbolAddress((void**)&ctx, g_ctx);
    cudaGetSymbolAddress((void**)&h1, g_h1);
    cudaGetSymbolAddress((void**)&ctxt, g_ctxt);
    cudaGetSymbolAddress((void**)&qm, g_q);
    cudaGetSymbolAddress((void**)&attout, g_attout);
    cudaGetSymbolAddress((void**)&mh, g_mh);

    // 0. mask dtype sniff (deterministic, same inputs -> same result)
    detect_mask<<<1, 256>>>((const unsigned int*)mask);

    // 1. gathers + scalars
    build_x1<<<BB * PP, 128>>>(enc_row, enc_col, clockv, endt, loc_id, robot, hold, stage, W_dyn);
    build_g12<<<BB, 256>>>(enc_row, ll1, ll2);

    // 2. pm_emb = X1 @ W_pmcat^T          (16384, 512, K=1536)
    gemm(X1, W_pmcat, pm_emb, BB * PP, DD, 3 * DD, DD, 0, nullptr, false);

    // 3. action tensor + context gathers
    build_action<<<BB * AA, 128>>>(enc_row, ll1, ll2, hold, W_time);
    pm_mean_rb<<<BB, 256>>>(robot);

    // 4. ctx = [ll_ctx | pm_ctx | rb_ctx]  (three GEMMs into one (B, 3D) buffer)
    gemm(g12, W_llctx, ctx, BB, DD, 2 * DD, 3 * DD, 0, nullptr, false);
    gemm(pmmean, W_pmctx, ctx, BB, DD, DD, 3 * DD, DD, nullptr, false);
    gemm(pmrb, W_rbctx, ctx, BB, DD, DD, 3 * DD, 2 * DD, nullptr, false);

    // 5. context MLP + q
    gemm(ctx, W_cc1, h1, BB, DD, 3 * DD, DD, 0, b_cc1, true);
    gemm(h1, W_cc2, ctxt, BB, DD, DD, DD, 0, b_cc2, false);
    gemm(ctxt, Wq, qm, BB, DD, DD, DD, 0, nullptr, false);

    // 6. K / V / SHK projections          (17408, 512, K=1536) each
    gemm(action, Wk, Km, BB * AA, DD, 3 * DD, DD, 0, nullptr, false);
    gemm(action, Wv, Vm, BB * AA, DD, 3 * DD, DD, 0, nullptr, false);
    gemm(action, Wshk, SHK, BB * AA, DD, 3 * DD, DD, 0, nullptr, false);

    // 7. attention -> attout, mh, final softmax
    attention<<<BB, HH * 32>>>(mask);
    gemm(attout, W_mhc, mh, BB, DD, DD, DD, 0, b_mhc, false);
    final_kernel<<<BB, 256>>>(mask, out);
}

// round 6
// speedup vs baseline: 2.6411x; 2.6411x over previous
#include <cuda_runtime.h>
#include <cuda_bf16.h>
#include <math.h>
#include <stdint.h>

#define BB 512
#define NW_ 256
#define NS_ 8
#define PP 32
#define DD 512
#define HH 16
#define QKD 32
#define AA 34
#define INV_NORM (1.0f/300.0f)
#define K3 1536

__device__ __forceinline__ uint32_t smem_u32(const void* p) {
    uint32_t a;
    asm("{ .reg .u64 t; cvta.to.shared.u64 t, %1; cvt.u32.u64 %0, t; }" : "=r"(a) : "l"(p));
    return a;
}

// ================= scratch =================
__device__ __align__(1024) __nv_bfloat16 g_X1b[(size_t)BB*PP*2*K3];
__device__ __align__(1024) __nv_bfloat16 g_act2[(size_t)BB*AA*2*K3];
__device__ __align__(1024) __nv_bfloat16 g_Wpm2[(size_t)DD*2*K3];
__device__ __align__(1024) __nv_bfloat16 g_Wkvs2[(size_t)3*DD*2*K3];
__device__ __align__(128) float g_pm_emb[(size_t)BB*PP*DD];
__device__ __align__(128) float g_KVS[(size_t)BB*AA*3*DD];
__device__ __align__(128) float g_g12[(size_t)BB*2*DD];
__device__ __align__(128) float g_pmmean[(size_t)BB*DD];
__device__ __align__(128) float g_pmrb[(size_t)BB*DD];
__device__ __align__(128) float g_ctx[(size_t)BB*3*DD];
__device__ __align__(128) float g_h1[(size_t)BB*DD];
__device__ __align__(128) float g_ctxt[(size_t)BB*DD];
__device__ __align__(128) float g_q[(size_t)BB*DD];
__device__ __align__(128) float g_attout[(size_t)BB*DD];
__device__ __align__(128) float g_mh[(size_t)BB*DD];
__device__ __align__(128) float g_dll[BB];
__device__ __align__(128) float g_dpm[BB*PP];
__device__ int g_mask_wordmode;

// ================= mask sniffer =================
__global__ void detect_mask(const unsigned int* __restrict__ mw)
{
    __shared__ int bad;
    if (threadIdx.x == 0) bad = 0;
    __syncthreads();
    for (int i = threadIdx.x; i < (BB * AA) / 4; i += blockDim.x) {
        unsigned int w = mw[i];
        if (w != 0u && w != 1u && w != 0x3F800000u) atomicExch(&bad, 1);
    }
    __syncthreads();
    if (threadIdx.x == 0) g_mask_wordmode = !bad;
}
__device__ __forceinline__ bool mask_at(const void* m, int i)
{
    if (g_mask_wordmode) return ((const unsigned int*)m)[i] != 0u;
    return ((const unsigned char*)m)[i] != 0u;
}

__device__ __forceinline__ void bsplit(float v, __nv_bfloat16* hi, __nv_bfloat16* lo)
{
    __nv_bfloat16 h = __float2bfloat16_rn(v);
    *hi = h;
    *lo = __float2bfloat16_rn(v - __bfloat162float(h));
}

// ================= bf16-split NT GEMM via mma.sync (HMMA, baseline PTX) ========
// C[M,N] = A[M,K]*B[N,K]^T using A,B stored as [hi|lo] rows of length 2K.
// 3 segments accumulate: Ah*Bh + Ah*Bl + Al*Bh. Tile 128x128, BK=64, 256 thr.
__global__ void __launch_bounds__(256) gemm_mma(
    const __nv_bfloat16* __restrict__ A2, const __nv_bfloat16* __restrict__ B2,
    float* __restrict__ C, int M, int K, int ldc)
{
    extern __shared__ char smem[];
    const uint32_t sb = smem_u32(smem);
    const int tid = threadIdx.x;
    const int lane = tid & 31;
    const int wid = tid >> 5;
    const int wm = wid >> 2;          // 0..1  (64-row slab)
    const int wn = wid & 3;           // 0..3  (32-col slab)
    const int bm = blockIdx.y * 128;
    const int bn = blockIdx.x * 128;
    const int lda = 2 * K;
    const uint32_t STAGE = 32768;     // A(16KB)+B(16KB)
    const int CH = K / 64;
    const int NIT = 3 * CH;

    float acc[4][4][4];
    #pragma unroll
    for (int i = 0; i < 4; i++)
        #pragma unroll
        for (int j = 0; j < 4; j++)
            #pragma unroll
            for (int r = 0; r < 4; r++) acc[i][j][r] = 0.f;

    // global load: 128 rows x 8 chunks(16B) per tile; 256 thr x 4 chunks each
    auto load_tiles = [&](int st, int it) {
        int seg = it / CH, kk = it - seg * CH;
        int aOff = (seg == 2 ? K : 0) + kk * 64;
        int bOff = (seg == 1 ? K : 0) + kk * 64;
        uint32_t ab = sb + st * STAGE;
        uint32_t bb = sb + st * STAGE + 16384;
        #pragma unroll
        for (int i = 0; i < 4; i++) {
            int idx = tid + i * 256;
            int row = idx >> 3, ch = idx & 7;
            uint32_t sw = (uint32_t)(row * 128 + ((ch ^ (row & 7)) << 4));
            const __nv_bfloat16* ag = A2 + (size_t)(bm + row) * lda + aOff + ch * 8;
            const __nv_bfloat16* bg = B2 + (size_t)(bn + row) * lda + bOff + ch * 8;
            asm volatile("cp.async.cg.shared.global [%0], [%1], 16;" :: "r"(ab + sw), "l"(ag));
            asm volatile("cp.async.cg.shared.global [%0], [%1], 16;" :: "r"(bb + sw), "l"(bg));
        }
    };

    load_tiles(0, 0);
    asm volatile("cp.async.commit_group;");

    for (int it = 0; it < NIT; ++it) {
        int st = it & 1;
        if (it + 1 < NIT) {
            load_tiles((it + 1) & 1, it + 1);
            asm volatile("cp.async.commit_group;");
            asm volatile("cp.async.wait_group 1;");
        } else {
            asm volatile("cp.async.wait_group 0;");
        }
        __syncthreads();

        uint32_t aB = sb + st * STAGE;
        uint32_t bB = sb + st * STAGE + 16384;
        #pragma unroll
        for (int kk8 = 0; kk8 < 8; kk8 += 2) {      // k-step of 16 bf16
            uint32_t ar[4][4], br[4][2];
            #pragma unroll
            for (int mf = 0; mf < 4; mf++) {
                int row = wm * 64 + mf * 16 + (lane & 15);
                int c = kk8 + (lane >> 4);
                uint32_t ad = aB + row * 128 + ((c ^ (row & 7)) << 4);
                asm volatile("ldmatrix.sync.aligned.m8n8.x4.shared.b16 {%0,%1,%2,%3}, [%4];"
                    : "=r"(ar[mf][0]), "=r"(ar[mf][1]), "=r"(ar[mf][2]), "=r"(ar[mf][3]) : "r"(ad));
            }
            #pragma unroll
            for (int nf = 0; nf < 4; nf++) {
                int nr = wn * 32 + nf * 8 + (lane & 7);
                int c = kk8 + ((lane >> 3) & 1);
                uint32_t bd = bB + nr * 128 + ((c ^ (nr & 7)) << 4);
                asm volatile("ldmatrix.sync.aligned.m8n8.x2.shared.b16 {%0,%1}, [%2];"
                    : "=r"(br[nf][0]), "=r"(br[nf][1]) : "r"(bd));
            }
            #pragma unroll
            for (int mf = 0; mf < 4; mf++)
                #pragma unroll
                for (int nf = 0; nf < 4; nf++) {
                    asm volatile(
                        "mma.sync.aligned.m16n8k16.row.col.f32.bf16.bf16.f32 "
                        "{%0,%1,%2,%3}, {%4,%5,%6,%7}, {%8,%9}, {%0,%1,%2,%3};"
                        : "+f"(acc[mf][nf][0]), "+f"(acc[mf][nf][1]),
                          "+f"(acc[mf][nf][2]), "+f"(acc[mf][nf][3])
                        : "r"(ar[mf][0]), "r"(ar[mf][1]), "r"(ar[mf][2]), "r"(ar[mf][3]),
                          "r"(br[nf][0]), "r"(br[nf][1]));
                }
        }
        __syncthreads();
    }

    // epilogue
    #pragma unroll
    for (int mf = 0; mf < 4; mf++) {
        int r0 = bm + wm * 64 + mf * 16 + (lane >> 2);
        #pragma unroll
        for (int nf = 0; nf < 4; nf++) {
            int c0 = bn + wn * 32 + nf * 8 + (lane & 3) * 2;
            float* p0 = C + (size_t)r0 * ldc + c0;
            float* p1 = C + (size_t)(r0 + 8) * ldc + c0;
            p0[0] = acc[mf][nf][0]; p0[1] = acc[mf][nf][1];
            p1[0] = acc[mf][nf][2]; p1[1] = acc[mf][nf][3];
        }
    }
}

// ================= fp32 NT SGEMM, 64x64 tile (small GEMMs; more CTAs) ==========
template<bool RELU>
__global__ void __launch_bounds__(256) sgemm64(
    const float* __restrict__ A, const float* __restrict__ Bm,
    float* __restrict__ C, int M, int N, int K,
    int ldc, int n0, const float* __restrict__ bias)
{
    __shared__ float As[16][64];
    __shared__ float Bs[16][64];
    const int tid = threadIdx.x;
    const int bm = blockIdx.y * 64;
    const int bn = blockIdx.x * 64;
    const int tx = tid & 15;
    const int ty = tid >> 4;
    const int lr = tid >> 2;         // 0..63
    const int lc = (tid & 3) * 4;    // 0,4,8,12

    float acc[4][4];
    #pragma unroll
    for (int i = 0; i < 4; i++)
        #pragma unroll
        for (int j = 0; j < 4; j++) acc[i][j] = 0.f;

    const float* Aptr = A + (size_t)(bm + lr) * K + lc;
    const float* Bptr = Bm + (size_t)(bn + lr) * K + lc;

    for (int k0 = 0; k0 < K; k0 += 16) {
        float4 av = *(const float4*)(Aptr + k0);
        float4 bv = *(const float4*)(Bptr + k0);
        __syncthreads();
        As[lc + 0][lr] = av.x; As[lc + 1][lr] = av.y;
        As[lc + 2][lr] = av.z; As[lc + 3][lr] = av.w;
        Bs[lc + 0][lr] = bv.x; Bs[lc + 1][lr] = bv.y;
        Bs[lc + 2][lr] = bv.z; Bs[lc + 3][lr] = bv.w;
        __syncthreads();
        #pragma unroll
        for (int kk = 0; kk < 16; kk++) {
            float a[4], b[4];
            *(float4*)a = *(const float4*)&As[kk][ty * 4];
            *(float4*)b = *(const float4*)&Bs[kk][tx * 4];
            #pragma unroll
            for (int i = 0; i < 4; i++)
                #pragma unroll
                for (int j = 0; j < 4; j++)
                    acc[i][j] = fmaf(a[i], b[j], acc[i][j]);
        }
    }
    #pragma unroll
    for (int i = 0; i < 4; i++) {
        int row = bm + ty * 4 + i;
        #pragma unroll
        for (int j = 0; j < 4; j++) {
            int col = bn + tx * 4 + j;
            float v = acc[i][j];
            if (bias) v += bias[col];
            if (RELU) v = fmaxf(v, 0.f);
            C[(size_t)row * ldc + n0 + col] = v;
        }
    }
}

// ================= weight fp32 -> [hi|lo] bf16 =================
__global__ void wsplit(const float* __restrict__ W, __nv_bfloat16* __restrict__ dst,
                       int rows, int rowoff)
{
    int idx = blockIdx.x * blockDim.x + threadIdx.x;
    if (idx >= rows * K3) return;
    int r = idx / K3, c = idx - r * K3;
    __nv_bfloat16 hi, lo;
    bsplit(W[idx], &hi, &lo);
    size_t base = (size_t)(rowoff + r) * (2 * K3);
    dst[base + c] = hi;
    dst[base + K3 + c] = lo;
}

// ================= builders =================
__global__ void build_x1b(const float* __restrict__ enc_row, const float* __restrict__ enc_col,
                          const float* __restrict__ clockv, const float* __restrict__ endt,
                          const int* __restrict__ loc_id, const int* __restrict__ robot,
                          const int* __restrict__ hold, const int* __restrict__ stage,
                          const float* __restrict__ Wdyn)
{
    int blk = blockIdx.x;
    int b = blk >> 5, p = blk & 31;
    float ck = clockv[b];
    float et = endt[b * PP + p];
    float remain = fmaxf(et - ck, 0.f) * INV_NORM;
    int st = stage[b * PP + p] - 1;
    int hw = hold[b * PP + p];
    __nv_bfloat16* row = g_X1b + (size_t)blk * (2 * K3);
    const float* cs = enc_col + ((size_t)b * NS_ + st) * DD;
    const float* ws = (hw >= 0) ? enc_row + ((size_t)b * NW_ + hw) * DD : nullptr;
    for (int d = threadIdx.x; d < DD; d += blockDim.x) {
        __nv_bfloat16 hi, lo;
        bsplit(cs[d], &hi, &lo);                 row[d] = hi;           row[K3 + d] = lo;
        bsplit(ws ? ws[d] : 0.f, &hi, &lo);      row[DD + d] = hi;      row[K3 + DD + d] = lo;
        bsplit(remain * Wdyn[2 * d], &hi, &lo);  row[2 * DD + d] = hi;  row[K3 + 2 * DD + d] = lo;
    }
    if (threadIdx.x == 0) {
        int rb = robot[b];
        float pk = ck + 3.f * (loc_id[b * PP + p] != rb);
        g_dpm[blk] = (fmaxf(et, pk) + 9.f - ck) * INV_NORM;
        if (p == 0) g_dll[b] = (3.f * (rb != 0) + 9.f) * INV_NORM;
    }
}

__global__ void build_g12(const float* __restrict__ enc_row,
                          const int* __restrict__ ll1, const int* __restrict__ ll2)
{
    int b = blockIdx.x;
    const float* r1 = enc_row + ((size_t)b * NW_ + ll1[b]) * DD;
    const float* r2 = enc_row + ((size_t)b * NW_ + ll2[b]) * DD;
    float* dst = g_g12 + (size_t)b * 2 * DD;
    for (int d = threadIdx.x; d < DD; d += blockDim.x) {
        dst[d] = r1[d];
        dst[DD + d] = r2[d];
    }
}

__global__ void build_actionb(const float* __restrict__ enc_row,
                              const int* __restrict__ ll1, const int* __restrict__ ll2,
                              const int* __restrict__ hold, const float* __restrict__ Wtime)
{
    int blk = blockIdx.x;
    int b = blk / AA, j = blk - b * AA;
    __nv_bfloat16* row = g_act2 + (size_t)blk * (2 * K3);
    if (j < 2) {
        int rec = (j == 0) ? ll1[b] : ll2[b];
        const float* g = enc_row + ((size_t)b * NW_ + rec) * DD;
        float dl = g_dll[b];
        for (int d = threadIdx.x; d < DD; d += blockDim.x) {
            __nv_bfloat16 z = __float2bfloat16_rn(0.f), hi, lo;
            row[d] = z; row[K3 + d] = z;
            bsplit(g[d], &hi, &lo);            row[DD + d] = hi;      row[K3 + DD + d] = lo;
            bsplit(dl * Wtime[d], &hi, &lo);   row[2 * DD + d] = hi;  row[K3 + 2 * DD + d] = lo;
        }
    } else {
        int p = j - 2;
        int hw = hold[b * PP + p];
        const float* ws = (hw >= 0) ? enc_row + ((size_t)b * NW_ + hw) * DD : nullptr;
        const float* pe = g_pm_emb + (size_t)(b * PP + p) * DD;
        float dp = g_dpm[b * PP + p];
        for (int d = threadIdx.x; d < DD; d += blockDim.x) {
            __nv_bfloat16 hi, lo;
            bsplit(pe[d], &hi, &lo);            row[d] = hi;           row[K3 + d] = lo;
            bsplit(ws ? ws[d] : 0.f, &hi, &lo); row[DD + d] = hi;      row[K3 + DD + d] = lo;
            bsplit(dp * Wtime[d], &hi, &lo);    row[2 * DD + d] = hi;  row[K3 + 2 * DD + d] = lo;
        }
    }
}

__global__ void pm_mean_rb(const int* __restrict__ robot)
{
    int b = blockIdx.x;
    int rb = robot[b];
    for (int d = threadIdx.x; d < DD; d += blockDim.x) {
        float s = 0.f;
        #pragma unroll 8
        for (int p = 0; p < PP; p++)
            s += g_pm_emb[((size_t)(b * PP + p)) * DD + d];
        g_pmmean[(size_t)b * DD + d] = s * (1.f / PP);
        g_pmrb[(size_t)b * DD + d] = g_pm_emb[((size_t)(b * PP + rb)) * DD + d];
    }
}

// ================= attention over g_KVS [K|V|SHK] (ld=1536) =================
__global__ void attention(const void* __restrict__ mask)
{
    int b = blockIdx.x;
    int h = threadIdx.x >> 5, lane = threadIdx.x & 31;
    __shared__ float ps[HH][AA + 2];
    float q = g_q[(size_t)b * DD + h * QKD + lane];
    const float scale = rsqrtf((float)QKD);
    for (int j = 0; j < AA; j++) {
        float kv = g_KVS[((size_t)(b * AA + j)) * (3 * DD) + h * QKD + lane];
        float s = q * kv;
        #pragma unroll
        for (int o = 16; o > 0; o >>= 1) s += __shfl_xor_sync(0xffffffffu, s, o);
        if (lane == 0) ps[h][j] = s * scale + (mask_at(mask, b * AA + j) ? 0.f : -1e10f);
    }
    __syncwarp();
    float m = -INFINITY;
    for (int j = 0; j < AA; j++) m = fmaxf(m, ps[h][j]);
    float sum = 0.f;
    for (int j = 0; j < AA; j++) sum += expf(ps[h][j] - m);
    float inv = 1.f / sum;
    float o = 0.f;
    for (int j = 0; j < AA; j++)
        o += expf(ps[h][j] - m) * inv * g_KVS[((size_t)(b * AA + j)) * (3 * DD) + DD + h * QKD + lane];
    g_attout[(size_t)b * DD + h * QKD + lane] = o;
}

__global__ void final_kernel(const void* __restrict__ mask, float* __restrict__ out)
{
    int b = blockIdx.x;
    int w = threadIdx.x >> 5, lane = threadIdx.x & 31;
    __shared__ float sc[AA];
    const float* mh = g_mh + (size_t)b * DD;
    const float scale = rsqrtf((float)DD);
    for (int a = w; a < AA; a += 8) {
        const float* s = g_KVS + ((size_t)(b * AA + a)) * (3 * DD) + 2 * DD;
        float acc = 0.f;
        for (int d = lane; d < DD; d += 32) acc = fmaf(mh[d], s[d], acc);
        #pragma unroll
        for (int o = 16; o > 0; o >>= 1) acc += __shfl_xor_sync(0xffffffffu, acc, o);
        if (lane == 0)
            sc[a] = 10.f * tanhf(acc * scale) + (mask_at(mask, b * AA + a) ? 0.f : -1e10f);
    }
    __syncthreads();
    if (threadIdx.x < AA) {
        float m = -INFINITY;
        for (int j = 0; j < AA; j++) m = fmaxf(m, sc[j]);
        float sum = 0.f;
        for (int j = 0; j < AA; j++) sum += expf(sc[j] - m);
        out[b * AA + threadIdx.x] = expf(sc[threadIdx.x] - m) / sum;
    }
}

// ================= launch =================
static inline void gemm_s(const float* A, const float* Bm, float* C,
                          int M, int N, int K, int ldc, int n0,
                          const float* bias, bool relu)
{
    dim3 grid(N / 64, M / 64);
    if (relu) sgemm64<true><<<grid, 256>>>(A, Bm, C, M, N, K, ldc, n0, bias);
    else      sgemm64<false><<<grid, 256>>>(A, Bm, C, M, N, K, ldc, n0, bias);
}

extern "C" void kernel_launch(void* const* d_in, const int* in_sizes, int n_in,
                              void* d_out, int out_size)
{
    const float* enc_row = (const float*)d_in[0];
    const float* enc_col = (const float*)d_in[1];
    const float* clockv  = (const float*)d_in[2];
    const float* endt    = (const float*)d_in[3];
    const int* loc_id    = (const int*)d_in[4];
    const int* robot     = (const int*)d_in[5];
    const int* hold      = (const int*)d_in[6];
    const int* stage     = (const int*)d_in[7];
    const int* ll1       = (const int*)d_in[8];
    const int* ll2       = (const int*)d_in[9];
    const void* mask     = d_in[10];
    const float* W_dyn   = (const float*)d_in[11];
    const float* W_pmcat = (const float*)d_in[12];
    const float* W_time  = (const float*)d_in[13];
    const float* W_llctx = (const float*)d_in[14];
    const float* W_pmctx = (const float*)d_in[15];
    const float* W_rbctx = (const float*)d_in[16];
    const float* W_cc1   = (const float*)d_in[17];
    const float* b_cc1   = (const float*)d_in[18];
    const float* W_cc2   = (const float*)d_in[19];
    const float* b_cc2   = (const float*)d_in[20];
    const float* Wq      = (const float*)d_in[21];
    const float* Wk      = (const float*)d_in[22];
    const float* Wv      = (const float*)d_in[23];
    const float* Wshk    = (const float*)d_in[24];
    const float* W_mhc   = (const float*)d_in[25];
    const float* b_mhc   = (const float*)d_in[26];
    float* out = (float*)d_out;

    __nv_bfloat16 *X1b, *act2, *Wpm2, *Wkvs2;
    float *pm_emb, *KVS, *g12, *pmmean, *pmrb, *ctx, *h1, *ctxt, *qm, *attout, *mh;
    cudaGetSymbolAddress((void**)&X1b, g_X1b);
    cudaGetSymbolAddress((void**)&act2, g_act2);
    cudaGetSymbolAddress((void**)&Wpm2, g_Wpm2);
    cudaGetSymbolAddress((void**)&Wkvs2, g_Wkvs2);
    cudaGetSymbolAddress((void**)&pm_emb, g_pm_emb);
    cudaGetSymbolAddress((void**)&KVS, g_KVS);
    cudaGetSymbolAddress((void**)&g12, g_g12);
    cudaGetSymbolAddress((void**)&pmmean, g_pmmean);
    cudaGetSymbolAddress((void**)&pmrb, g_pmrb);
    cudaGetSymbolAddress((void**)&ctx, g_ctx);
    cudaGetSymbolAddress((void**)&h1, g_h1);
    cudaGetSymbolAddress((void**)&ctxt, g_ctxt);
    cudaGetSymbolAddress((void**)&qm, g_q);
    cudaGetSymbolAddress((void**)&attout, g_attout);
    cudaGetSymbolAddress((void**)&mh, g_mh);

    const int MMA_SMEM = 65536;
    cudaFuncSetAttribute(gemm_mma, cudaFuncAttributeMaxDynamicSharedMemorySize, MMA_SMEM);

    // 0. mask dtype sniff
    detect_mask<<<1, 256>>>((const unsigned int*)mask);

    // 1. builders + weight splits
    build_x1b<<<BB * PP, 128>>>(enc_row, enc_col, clockv, endt, loc_id, robot, hold, stage, W_dyn);
    build_g12<<<BB, 256>>>(enc_row, ll1, ll2);
    {
        int n = DD * K3, thr = 256, blocks = (n + thr - 1) / thr;
        wsplit<<<blocks, thr>>>(W_pmcat, Wpm2, DD, 0);
        wsplit<<<blocks, thr>>>(Wk,   Wkvs2, DD, 0);
        wsplit<<<blocks, thr>>>(Wv,   Wkvs2, DD, DD);
        wsplit<<<blocks, thr>>>(Wshk, Wkvs2, DD, 2 * DD);
    }

    // 2. pm_emb = X1 @ W_pmcat^T   (HMMA, 16384x512x1536)
    gemm_mma<<<dim3(DD / 128, BB * PP / 128), 256, MMA_SMEM>>>(X1b, Wpm2, pm_emb, BB * PP, K3, DD);

    // 3. action + context gathers
    build_actionb<<<BB * AA, 128>>>(enc_row, ll1, ll2, hold, W_time);
    pm_mean_rb<<<BB, 256>>>(robot);

    // 4. ctx = [ll_ctx | pm_ctx | rb_ctx]
    gemm_s(g12, W_llctx, ctx, BB, DD, 2 * DD, 3 * DD, 0, nullptr, false);
    gemm_s(pmmean, W_pmctx, ctx, BB, DD, DD, 3 * DD, DD, nullptr, false);
    gemm_s(pmrb, W_rbctx, ctx, BB, DD, DD, 3 * DD, 2 * DD, nullptr, false);

    // 5. context MLP + q
    gemm_s(ctx, W_cc1, h1, BB, DD, 3 * DD, DD, 0, b_cc1, true);
    gemm_s(h1, W_cc2, ctxt, BB, DD, DD, DD, 0, b_cc2, false);
    gemm_s(ctxt, Wq, qm, BB, DD, DD, DD, 0, nullptr, false);

    // 6. fused K|V|SHK projection  (HMMA, 17408x1536x1536)
    gemm_mma<<<dim3(3 * DD / 128, BB * AA / 128), 256, MMA_SMEM>>>(act2, Wkvs2, KVS, BB * AA, K3, 3 * DD);

    // 7. attention -> mh -> final softmax
    attention<<<BB, HH * 32>>>(mask);
    gemm_s(attout, W_mhc, mh, BB, DD, DD, DD, 0, b_mhc, false);
    final_kernel<<<BB, 256>>>(mask, out);
}

// round 10
// speedup vs baseline: 3.8955x; 1.4750x over previous
#include <cuda_runtime.h>
#include <cuda_fp16.h>
#include <math.h>
#include <stdint.h>

#define BB 512
#define NW_ 256
#define NS_ 8
#define PP 32
#define DD 512
#define HH 16
#define QKD 32
#define AA 34
#define INV_NORM (1.0f/300.0f)
#define K3 1536

__device__ __forceinline__ uint32_t smem_u32(const void* p) {
    uint32_t a;
    asm("{ .reg .u64 t; cvta.to.shared.u64 t, %1; cvt.u32.u64 %0, t; }" : "=r"(a) : "l"(p));
    return a;
}

// ================= scratch =================
__device__ __align__(1024) __half g_X1h[(size_t)BB*PP*K3];        // (16384, 1536) fp16
__device__ __align__(1024) __half g_acth[(size_t)BB*AA*K3];       // (17408, 1536) fp16
__device__ __align__(1024) __half g_Wpm2[(size_t)DD*2*K3];        // (512, [hi|lo] 3072)
__device__ __align__(1024) __half g_Wkvs2[(size_t)3*DD*2*K3];     // (1536, [hi|lo] 3072)
__device__ __align__(128) float g_pm_emb[(size_t)BB*PP*DD];
__device__ __align__(128) float g_KVS[(size_t)BB*AA*3*DD];
__device__ __align__(128) float g_g12[(size_t)BB*2*DD];
__device__ __align__(128) float g_pmmean[(size_t)BB*DD];
__device__ __align__(128) float g_pmrb[(size_t)BB*DD];
__device__ __align__(128) float g_ctx[(size_t)BB*3*DD];
__device__ __align__(128) float g_h1[(size_t)BB*DD];
__device__ __align__(128) float g_ctxt[(size_t)BB*DD];
__device__ __align__(128) float g_q[(size_t)BB*DD];
__device__ __align__(128) float g_attout[(size_t)BB*DD];
__device__ __align__(128) float g_mh[(size_t)BB*DD];
__device__ __align__(128) float g_dll[BB];
__device__ __align__(128) float g_dpm[BB*PP];
__device__ int g_mask_wordmode;

// ================= mask sniffer =================
__global__ void detect_mask(const unsigned int* __restrict__ mw)
{
    __shared__ int bad;
    if (threadIdx.x == 0) bad = 0;
    __syncthreads();
    for (int i = threadIdx.x; i < (BB * AA) / 4; i += blockDim.x) {
        unsigned int w = mw[i];
        if (w != 0u && w != 1u && w != 0x3F800000u) atomicExch(&bad, 1);
    }
    __syncthreads();
    if (threadIdx.x == 0) g_mask_wordmode = !bad;
}
__device__ __forceinline__ bool mask_at(const void* m, int i)
{
    if (g_mask_wordmode) return ((const unsigned int*)m)[i] != 0u;
    return ((const unsigned char*)m)[i] != 0u;
}

__device__ __forceinline__ void hsplit(float v, __half* hi, __half* lo)
{
    __half h = __float2half_rn(v);
    *hi = h;
    *lo = __float2half_rn(v - __half2float(h));
}

// ================= fp16 weight-split NT GEMM via mma.sync =================
// C[M,N] = A[M,K] * B[N,K]^T.  A fp16 (lda=K).  B stored [hi|lo] (ldb=2K).
// C = A*Bh + A*Bl accumulated in fp32. Tile 128x128, BK=64, 256 thr.
// SMEM per stage: A 16KB | Bh 16KB | Bl 16KB = 48KB; 2 stages.
__global__ void __launch_bounds__(256) gemm_mma(
    const __half* __restrict__ A, const __half* __restrict__ B2,
    float* __restrict__ C, int M, int K, int ldc)
{
    extern __shared__ char smem[];
    const uint32_t sb = smem_u32(smem);
    const int tid = threadIdx.x;
    const int lane = tid & 31;
    const int wid = tid >> 5;
    const int wm = wid >> 2;          // 0..1
    const int wn = wid & 3;           // 0..3
    const int bm = blockIdx.y * 128;
    const int bn = blockIdx.x * 128;
    const int ldb = 2 * K;
    const uint32_t STAGE = 49152;
    const int CH = K / 64;

    float acc[4][4][4];
    #pragma unroll
    for (int i = 0; i < 4; i++)
        #pragma unroll
        for (int j = 0; j < 4; j++)
            #pragma unroll
            for (int r = 0; r < 4; r++) acc[i][j][r] = 0.f;

    auto load_tiles = [&](int st, int kk) {
        uint32_t ab = sb + st * STAGE;
        uint32_t hb = ab + 16384;
        uint32_t lb = ab + 32768;
        #pragma unroll
        for (int i = 0; i < 4; i++) {
            int idx = tid + i * 256;
            int row = idx >> 3, ch = idx & 7;
            uint32_t sw = (uint32_t)(row * 128 + ((ch ^ (row & 7)) << 4));
            const __half* ag = A  + (size_t)(bm + row) * K   + kk * 64 + ch * 8;
            const __half* hg = B2 + (size_t)(bn + row) * ldb + kk * 64 + ch * 8;
            const __half* lg = B2 + (size_t)(bn + row) * ldb + K + kk * 64 + ch * 8;
            asm volatile("cp.async.cg.shared.global [%0], [%1], 16;" :: "r"(ab + sw), "l"(ag));
            asm volatile("cp.async.cg.shared.global [%0], [%1], 16;" :: "r"(hb + sw), "l"(hg));
            asm volatile("cp.async.cg.shared.global [%0], [%1], 16;" :: "r"(lb + sw), "l"(lg));
        }
    };

    load_tiles(0, 0);
    asm volatile("cp.async.commit_group;");

    for (int it = 0; it < CH; ++it) {
        int st = it & 1;
        if (it + 1 < CH) {
            load_tiles((it + 1) & 1, it + 1);
            asm volatile("cp.async.commit_group;");
            asm volatile("cp.async.wait_group 1;");
        } else {
            asm volatile("cp.async.wait_group 0;");
        }
        __syncthreads();

        uint32_t aB = sb + st * STAGE;
        uint32_t hB = aB + 16384;
        uint32_t lB = aB + 32768;
        #pragma unroll
        for (int kk8 = 0; kk8 < 8; kk8 += 2) {
            uint32_t ar[4][4], bh[4][2], bl[4][2];
            #pragma unroll
            for (int mf = 0; mf < 4; mf++) {
                int row = wm * 64 + mf * 16 + (lane & 15);
                int c = kk8 + (lane >> 4);
                uint32_t ad = aB + row * 128 + ((c ^ (row & 7)) << 4);
                asm volatile("ldmatrix.sync.aligned.m8n8.x4.shared.b16 {%0,%1,%2,%3}, [%4];"
                    : "=r"(ar[mf][0]), "=r"(ar[mf][1]), "=r"(ar[mf][2]), "=r"(ar[mf][3]) : "r"(ad));
            }
            #pragma unroll
            for (int nf = 0; nf < 4; nf++) {
                int nr = wn * 32 + nf * 8 + (lane & 7);
                int c = kk8 + ((lane >> 3) & 1);
                uint32_t off = nr * 128 + ((c ^ (nr & 7)) << 4);
                asm volatile("ldmatrix.sync.aligned.m8n8.x2.shared.b16 {%0,%1}, [%2];"
                    : "=r"(bh[nf][0]), "=r"(bh[nf][1]) : "r"(hB + off));
                asm volatile("ldmatrix.sync.aligned.m8n8.x2.shared.b16 {%0,%1}, [%2];"
                    : "=r"(bl[nf][0]), "=r"(bl[nf][1]) : "r"(lB + off));
            }
            #pragma unroll
            for (int mf = 0; mf < 4; mf++)
                #pragma unroll
                for (int nf = 0; nf < 4; nf++) {
                    asm volatile(
                        "mma.sync.aligned.m16n8k16.row.col.f32.f16.f16.f32 "
                        "{%0,%1,%2,%3}, {%4,%5,%6,%7}, {%8,%9}, {%0,%1,%2,%3};"
                        : "+f"(acc[mf][nf][0]), "+f"(acc[mf][nf][1]),
                          "+f"(acc[mf][nf][2]), "+f"(acc[mf][nf][3])
                        : "r"(ar[mf][0]), "r"(ar[mf][1]), "r"(ar[mf][2]), "r"(ar[mf][3]),
                          "r"(bh[nf][0]), "r"(bh[nf][1]));
                    asm volatile(
                        "mma.sync.aligned.m16n8k16.row.col.f32.f16.f16.f32 "
                        "{%0,%1,%2,%3}, {%4,%5,%6,%7}, {%8,%9}, {%0,%1,%2,%3};"
                        : "+f"(acc[mf][nf][0]), "+f"(acc[mf][nf][1]),
                          "+f"(acc[mf][nf][2]), "+f"(acc[mf][nf][3])
                        : "r"(ar[mf][0]), "r"(ar[mf][1]), "r"(ar[mf][2]), "r"(ar[mf][3]),
                          "r"(bl[nf][0]), "r"(bl[nf][1]));
                }
        }
        __syncthreads();
    }

    #pragma unroll
    for (int mf = 0; mf < 4; mf++) {
        int r0 = bm + wm * 64 + mf * 16 + (lane >> 2);
        #pragma unroll
        for (int nf = 0; nf < 4; nf++) {
            int c0 = bn + wn * 32 + nf * 8 + (lane & 3) * 2;
            float* p0 = C + (size_t)r0 * ldc + c0;
            float* p1 = C + (size_t)(r0 + 8) * ldc + c0;
            p0[0] = acc[mf][nf][0]; p0[1] = acc[mf][nf][1];
            p1[0] = acc[mf][nf][2]; p1[1] = acc[mf][nf][3];
        }
    }
}

// ================= fp32 NT SGEMM 64x64 (small GEMMs) =================
template<bool RELU>
__global__ void __launch_bounds__(256) sgemm64(
    const float* __restrict__ A, const float* __restrict__ Bm,
    float* __restrict__ C, int M, int N, int K,
    int ldc, int n0, const float* __restrict__ bias)
{
    __shared__ float As[16][64];
    __shared__ float Bs[16][64];
    const int tid = threadIdx.x;
    const int bm = blockIdx.y * 64;
    const int bn = blockIdx.x * 64;
    const int tx = tid & 15;
    const int ty = tid >> 4;
    const int lr = tid >> 2;
    const int lc = (tid & 3) * 4;

    float acc[4][4];
    #pragma unroll
    for (int i = 0; i < 4; i++)
        #pragma unroll
        for (int j = 0; j < 4; j++) acc[i][j] = 0.f;

    const float* Aptr = A + (size_t)(bm + lr) * K + lc;
    const float* Bptr = Bm + (size_t)(bn + lr) * K + lc;

    for (int k0 = 0; k0 < K; k0 += 16) {
        float4 av = *(const float4*)(Aptr + k0);
        float4 bv = *(const float4*)(Bptr + k0);
        __syncthreads();
        As[lc + 0][lr] = av.x; As[lc + 1][lr] = av.y;
        As[lc + 2][lr] = av.z; As[lc + 3][lr] = av.w;
        Bs[lc + 0][lr] = bv.x; Bs[lc + 1][lr] = bv.y;
        Bs[lc + 2][lr] = bv.z; Bs[lc + 3][lr] = bv.w;
        __syncthreads();
        #pragma unroll
        for (int kk = 0; kk < 16; kk++) {
            float a[4], b[4];
            *(float4*)a = *(const float4*)&As[kk][ty * 4];
            *(float4*)b = *(const float4*)&Bs[kk][tx * 4];
            #pragma unroll
            for (int i = 0; i < 4; i++)
                #pragma unroll
                for (int j = 0; j < 4; j++)
                    acc[i][j] = fmaf(a[i], b[j], acc[i][j]);
        }
    }
    #pragma unroll
    for (int i = 0; i < 4; i++) {
        int row = bm + ty * 4 + i;
        #pragma unroll
        for (int j = 0; j < 4; j++) {
            int col = bn + tx * 4 + j;
            float v = acc[i][j];
            if (bias) v += bias[col];
            if (RELU) v = fmaxf(v, 0.f);
            C[(size_t)row * ldc + n0 + col] = v;
        }
    }
}

// ================= weight fp32 -> [hi|lo] fp16 =================
__global__ void wsplit(const float* __restrict__ W, __half* __restrict__ dst,
                       int rows, int rowoff)
{
    int idx = blockIdx.x * blockDim.x + threadIdx.x;
    if (idx >= rows * K3) return;
    int r = idx / K3, c = idx - r * K3;
    __half hi, lo;
    hsplit(W[idx], &hi, &lo);
    size_t base = (size_t)(rowoff + r) * (2 * K3);
    dst[base + c] = hi;
    dst[base + K3 + c] = lo;
}

// ================= builders (fp16 single-precision activations) =================
__global__ void build_x1h(const float* __restrict__ enc_row, const float* __restrict__ enc_col,
                          const float* __restrict__ clockv, const float* __restrict__ endt,
                          const int* __restrict__ loc_id, const int* __restrict__ robot,
                          const int* __restrict__ hold, const int* __restrict__ stage,
                          const float* __restrict__ Wdyn)
{
    int blk = blockIdx.x;
    int b = blk >> 5, p = blk & 31;
    float ck = clockv[b];
    float et = endt[b * PP + p];
    float remain = fmaxf(et - ck, 0.f) * INV_NORM;
    int st = stage[b * PP + p] - 1;
    int hw = hold[b * PP + p];
    __half* row = g_X1h + (size_t)blk * K3;
    const float* cs = enc_col + ((size_t)b * NS_ + st) * DD;
    const float* ws = (hw >= 0) ? enc_row + ((size_t)b * NW_ + hw) * DD : nullptr;
    for (int d = threadIdx.x; d < DD; d += blockDim.x) {
        row[d] = __float2half_rn(cs[d]);
        row[DD + d] = __float2half_rn(ws ? ws[d] : 0.f);
        row[2 * DD + d] = __float2half_rn(remain * Wdyn[2 * d]);
    }
    if (threadIdx.x == 0) {
        int rb = robot[b];
        float pk = ck + 3.f * (loc_id[b * PP + p] != rb);
        g_dpm[blk] = (fmaxf(et, pk) + 9.f - ck) * INV_NORM;
        if (p == 0) g_dll[b] = (3.f * (rb != 0) + 9.f) * INV_NORM;
    }
}

__global__ void build_g12(const float* __restrict__ enc_row,
                          const int* __restrict__ ll1, const int* __restrict__ ll2)
{
    int b = blockIdx.x;
    const float* r1 = enc_row + ((size_t)b * NW_ + ll1[b]) * DD;
    const float* r2 = enc_row + ((size_t)b * NW_ + ll2[b]) * DD;
    float* dst = g_g12 + (size_t)b * 2 * DD;
    for (int d = threadIdx.x; d < DD; d += blockDim.x) {
        dst[d] = r1[d];
        dst[DD + d] = r2[d];
    }
}

__global__ void build_actionh(const float* __restrict__ enc_row,
                              const int* __restrict__ ll1, const int* __restrict__ ll2,
                              const int* __restrict__ hold, const float* __restrict__ Wtime)
{
    int blk = blockIdx.x;
    int b = blk / AA, j = blk - b * AA;
    __half* row = g_acth + (size_t)blk * K3;
    if (j < 2) {
        int rec = (j == 0) ? ll1[b] : ll2[b];
        const float* g = enc_row + ((size_t)b * NW_ + rec) * DD;
        float dl = g_dll[b];
        for (int d = threadIdx.x; d < DD; d += blockDim.x) {
            row[d] = __float2half_rn(0.f);
            row[DD + d] = __float2half_rn(g[d]);
            row[2 * DD + d] = __float2half_rn(dl * Wtime[d]);
        }
    } else {
        int p = j - 2;
        int hw = hold[b * PP + p];
        const float* ws = (hw >= 0) ? enc_row + ((size_t)b * NW_ + hw) * DD : nullptr;
        const float* pe = g_pm_emb + (size_t)(b * PP + p) * DD;
        float dp = g_dpm[b * PP + p];
        for (int d = threadIdx.x; d < DD; d += blockDim.x) {
            row[d] = __float2half_rn(pe[d]);
            row[DD + d] = __float2half_rn(ws ? ws[d] : 0.f);
            row[2 * DD + d] = __float2half_rn(dp * Wtime[d]);
        }
    }
}

__global__ void pm_mean_rb(const int* __restrict__ robot)
{
    int b = blockIdx.x;
    int rb = robot[b];
    for (int d = threadIdx.x; d < DD; d += blockDim.x) {
        float s = 0.f;
        #pragma unroll 8
        for (int p = 0; p < PP; p++)
            s += g_pm_emb[((size_t)(b * PP + p)) * DD + d];
        g_pmmean[(size_t)b * DD + d] = s * (1.f / PP);
        g_pmrb[(size_t)b * DD + d] = g_pm_emb[((size_t)(b * PP + rb)) * DD + d];
    }
}

// ================= attention over g_KVS [K|V|SHK] (ld=1536) =================
__global__ void attention(const void* __restrict__ mask)
{
    int b = blockIdx.x;
    int h = threadIdx.x >> 5, lane = threadIdx.x & 31;
    __shared__ float ps[HH][AA + 2];
    float q = g_q[(size_t)b * DD + h * QKD + lane];
    const float scale = rsqrtf((float)QKD);
    for (int j = 0; j < AA; j++) {
        float kv = g_KVS[((size_t)(b * AA + j)) * (3 * DD) + h * QKD + lane];
        float s = q * kv;
        #pragma unroll
        for (int o = 16; o > 0; o >>= 1) s += __shfl_xor_sync(0xffffffffu, s, o);
        if (lane == 0) ps[h][j] = s * scale + (mask_at(mask, b * AA + j) ? 0.f : -1e10f);
    }
    __syncwarp();
    float m = -INFINITY;
    for (int j = 0; j < AA; j++) m = fmaxf(m, ps[h][j]);
    float sum = 0.f;
    for (int j = 0; j < AA; j++) sum += expf(ps[h][j] - m);
    float inv = 1.f / sum;
    float o = 0.f;
    for (int j = 0; j < AA; j++)
        o += expf(ps[h][j] - m) * inv * g_KVS[((size_t)(b * AA + j)) * (3 * DD) + DD + h * QKD + lane];
    g_attout[(size_t)b * DD + h * QKD + lane] = o;
}

__global__ void final_kernel(const void* __restrict__ mask, float* __restrict__ out)
{
    int b = blockIdx.x;
    int w = threadIdx.x >> 5, lane = threadIdx.x & 31;
    __shared__ float sc[AA];
    const float* mh = g_mh + (size_t)b * DD;
    const float scale = rsqrtf((float)DD);
    for (int a = w; a < AA; a += 8) {
        const float* s = g_KVS + ((size_t)(b * AA + a)) * (3 * DD) + 2 * DD;
        float acc = 0.f;
        for (int d = lane; d < DD; d += 32) acc = fmaf(mh[d], s[d], acc);
        #pragma unroll
        for (int o = 16; o > 0; o >>= 1) acc += __shfl_xor_sync(0xffffffffu, acc, o);
        if (lane == 0)
            sc[a] = 10.f * tanhf(acc * scale) + (mask_at(mask, b * AA + a) ? 0.f : -1e10f);
    }
    __syncthreads();
    if (threadIdx.x < AA) {
        float m = -INFINITY;
        for (int j = 0; j < AA; j++) m = fmaxf(m, sc[j]);
        float sum = 0.f;
        for (int j = 0; j < AA; j++) sum += expf(sc[j] - m);
        out[b * AA + threadIdx.x] = expf(sc[threadIdx.x] - m) / sum;
    }
}

// ================= launch =================
static inline void gemm_s(const float* A, const float* Bm, float* C,
                          int M, int N, int K, int ldc, int n0,
                          const float* bias, bool relu)
{
    dim3 grid(N / 64, M / 64);
    if (relu) sgemm64<true><<<grid, 256>>>(A, Bm, C, M, N, K, ldc, n0, bias);
    else      sgemm64<false><<<grid, 256>>>(A, Bm, C, M, N, K, ldc, n0, bias);
}

extern "C" void kernel_launch(void* const* d_in, const int* in_sizes, int n_in,
                              void* d_out, int out_size)
{
    const float* enc_row = (const float*)d_in[0];
    const float* enc_col = (const float*)d_in[1];
    const float* clockv  = (const float*)d_in[2];
    const float* endt    = (const float*)d_in[3];
    const int* loc_id    = (const int*)d_in[4];
    const int* robot     = (const int*)d_in[5];
    const int* hold      = (const int*)d_in[6];
    const int* stage     = (const int*)d_in[7];
    const int* ll1       = (const int*)d_in[8];
    const int* ll2       = (const int*)d_in[9];
    const void* mask     = d_in[10];
    const float* W_dyn   = (const float*)d_in[11];
    const float* W_pmcat = (const float*)d_in[12];
    const float* W_time  = (const float*)d_in[13];
    const float* W_llctx = (const float*)d_in[14];
    const float* W_pmctx = (const float*)d_in[15];
    const float* W_rbctx = (const float*)d_in[16];
    const float* W_cc1   = (const float*)d_in[17];
    const float* b_cc1   = (const float*)d_in[18];
    const float* W_cc2   = (const float*)d_in[19];
    const float* b_cc2   = (const float*)d_in[20];
    const float* Wq      = (const float*)d_in[21];
    const float* Wk      = (const float*)d_in[22];
    const float* Wv      = (const float*)d_in[23];
    const float* Wshk    = (const float*)d_in[24];
    const float* W_mhc   = (const float*)d_in[25];
    const float* b_mhc   = (const float*)d_in[26];
    float* out = (float*)d_out;

    __half *X1h, *acth, *Wpm2, *Wkvs2;
    float *pm_emb, *KVS, *g12, *pmmean, *pmrb, *ctx, *h1, *ctxt, *qm, *attout, *mh;
    cudaGetSymbolAddress((void**)&X1h, g_X1h);
    cudaGetSymbolAddress((void**)&acth, g_acth);
    cudaGetSymbolAddress((void**)&Wpm2, g_Wpm2);
    cudaGetSymbolAddress((void**)&Wkvs2, g_Wkvs2);
    cudaGetSymbolAddress((void**)&pm_emb, g_pm_emb);
    cudaGetSymbolAddress((void**)&KVS, g_KVS);
    cudaGetSymbolAddress((void**)&g12, g_g12);
    cudaGetSymbolAddress((void**)&pmmean, g_pmmean);
    cudaGetSymbolAddress((void**)&pmrb, g_pmrb);
    cudaGetSymbolAddress((void**)&ctx, g_ctx);
    cudaGetSymbolAddress((void**)&h1, g_h1);
    cudaGetSymbolAddress((void**)&ctxt, g_ctxt);
    cudaGetSymbolAddress((void**)&qm, g_q);
    cudaGetSymbolAddress((void**)&attout, g_attout);
    cudaGetSymbolAddress((void**)&mh, g_mh);

    const int MMA_SMEM = 98304;  // 2 stages x 48KB
    cudaFuncSetAttribute(gemm_mma, cudaFuncAttributeMaxDynamicSharedMemorySize, MMA_SMEM);

    // 0. mask dtype sniff
    detect_mask<<<1, 256>>>((const unsigned int*)mask);

    // 1. builders + weight splits
    build_x1h<<<BB * PP, 128>>>(enc_row, enc_col, clockv, endt, loc_id, robot, hold, stage, W_dyn);
    build_g12<<<BB, 256>>>(enc_row, ll1, ll2);
    {
        int n = DD * K3, thr = 256, blocks = (n + thr - 1) / thr;
        wsplit<<<blocks, thr>>>(W_pmcat, Wpm2, DD, 0);
        wsplit<<<blocks, thr>>>(Wk,   Wkvs2, DD, 0);
        wsplit<<<blocks, thr>>>(Wv,   Wkvs2, DD, DD);
        wsplit<<<blocks, thr>>>(Wshk, Wkvs2, DD, 2 * DD);
    }

    // 2. pm_emb = X1 @ W_pmcat^T  (HMMA fp16 2-pass, 16384x512x1536)
    gemm_mma<<<dim3(DD / 128, BB * PP / 128), 256, MMA_SMEM>>>(X1h, Wpm2, pm_emb, BB * PP, K3, DD);

    // 3. action + context gathers
    build_actionh<<<BB * AA, 128>>>(enc_row, ll1, ll2, hold, W_time);
    pm_mean_rb<<<BB, 256>>>(robot);

    // 4. ctx = [ll_ctx | pm_ctx | rb_ctx]
    gemm_s(g12, W_llctx, ctx, BB, DD, 2 * DD, 3 * DD, 0, nullptr, false);
    gemm_s(pmmean, W_pmctx, ctx, BB, DD, DD, 3 * DD, DD, nullptr, false);
    gemm_s(pmrb, W_rbctx, ctx, BB, DD, DD, 3 * DD, 2 * DD, nullptr, false);

    // 5. context MLP + q
    gemm_s(ctx, W_cc1, h1, BB, DD, 3 * DD, DD, 0, b_cc1, true);
    gemm_s(h1, W_cc2, ctxt, BB, DD, DD, DD, 0, b_cc2, false);
    gemm_s(ctxt, Wq, qm, BB, DD, DD, DD, 0, nullptr, false);

    // 6. fused K|V|SHK projection  (HMMA fp16 2-pass, 17408x1536x1536)
    gemm_mma<<<dim3(3 * DD / 128, BB * AA / 128), 256, MMA_SMEM>>>(acth, Wkvs2, KVS, BB * AA, K3, 3 * DD);

    // 7. attention -> mh -> final softmax
    attention<<<BB, HH * 32>>>(mask);
    gemm_s(attout, W_mhc, mh, BB, DD, DD, DD, 0, b_mhc, false);
    final_kernel<<<BB, 256>>>(mask, out);
}

// round 11
// speedup vs baseline: 4.7429x; 1.2175x over previous
#include <cuda_runtime.h>
#include <cuda_fp16.h>
#include <math.h>
#include <stdint.h>

#define BB 512
#define NW_ 256
#define NS_ 8
#define PP 32
#define DD 512
#define HH 16
#define QKD 32
#define AA 34
#define INV_NORM (1.0f/300.0f)
#define K3 1536

__device__ __forceinline__ uint32_t smem_u32(const void* p) {
    uint32_t a;
    asm("{ .reg .u64 t; cvta.to.shared.u64 t, %1; cvt.u32.u64 %0, t; }" : "=r"(a) : "l"(p));
    return a;
}

// ================= scratch =================
__device__ __align__(1024) __half g_X1h[(size_t)BB*PP*K3];        // (16384, 1536)
__device__ __align__(1024) __half g_acth[(size_t)BB*AA*K3];       // (17408, 1536)
__device__ __align__(1024) __half g_Wpmh[(size_t)DD*K3];          // (512, 1536)
__device__ __align__(1024) __half g_Wkvsh[(size_t)3*DD*K3];       // (1536, 1536)
__device__ __align__(128) float g_pm_emb[(size_t)BB*PP*DD];
__device__ __align__(128) float g_KVS[(size_t)BB*AA*3*DD];
__device__ __align__(128) float g_g12[(size_t)BB*2*DD];
__device__ __align__(128) float g_pmmean[(size_t)BB*DD];
__device__ __align__(128) float g_pmrb[(size_t)BB*DD];
__device__ __align__(128) float g_ctx[(size_t)BB*3*DD];
__device__ __align__(128) float g_h1[(size_t)BB*DD];
__device__ __align__(128) float g_ctxt[(size_t)BB*DD];
__device__ __align__(128) float g_q[(size_t)BB*DD];
__device__ __align__(128) float g_attout[(size_t)BB*DD];
__device__ __align__(128) float g_mh[(size_t)BB*DD];
__device__ __align__(128) float g_dll[BB];
__device__ __align__(128) float g_dpm[BB*PP];
__device__ int g_mask_wordmode;

// ================= mask sniffer =================
__global__ void detect_mask(const unsigned int* __restrict__ mw)
{
    __shared__ int bad;
    if (threadIdx.x == 0) bad = 0;
    __syncthreads();
    for (int i = threadIdx.x; i < (BB * AA) / 4; i += blockDim.x) {
        unsigned int w = mw[i];
        if (w != 0u && w != 1u && w != 0x3F800000u) atomicExch(&bad, 1);
    }
    __syncthreads();
    if (threadIdx.x == 0) g_mask_wordmode = !bad;
}
__device__ __forceinline__ bool mask_at(const void* m, int i)
{
    if (g_mask_wordmode) return ((const unsigned int*)m)[i] != 0u;
    return ((const unsigned char*)m)[i] != 0u;
}

// ================= fp16 single-pass NT GEMM via mma.sync =================
// C[M,N] = A[M,K] * B[N,K]^T, both fp16, fp32 accum. Tile 128x128, BK=64.
// SMEM per stage: A 16KB + B 16KB = 32KB; 2 stages.
__global__ void __launch_bounds__(256) gemm_mma(
    const __half* __restrict__ A, const __half* __restrict__ Bm,
    float* __restrict__ C, int M, int K, int ldc)
{
    extern __shared__ char smem[];
    const uint32_t sb = smem_u32(smem);
    const int tid = threadIdx.x;
    const int lane = tid & 31;
    const int wid = tid >> 5;
    const int wm = wid >> 2;          // 0..1
    const int wn = wid & 3;           // 0..3
    const int bm = blockIdx.y * 128;
    const int bn = blockIdx.x * 128;
    const uint32_t STAGE = 32768;
    const int CH = K / 64;

    float acc[4][4][4];
    #pragma unroll
    for (int i = 0; i < 4; i++)
        #pragma unroll
        for (int j = 0; j < 4; j++)
            #pragma unroll
            for (int r = 0; r < 4; r++) acc[i][j][r] = 0.f;

    auto load_tiles = [&](int st, int kk) {
        uint32_t ab = sb + st * STAGE;
        uint32_t bb = ab + 16384;
        #pragma unroll
        for (int i = 0; i < 4; i++) {
            int idx = tid + i * 256;
            int row = idx >> 3, ch = idx & 7;
            uint32_t sw = (uint32_t)(row * 128 + ((ch ^ (row & 7)) << 4));
            const __half* ag = A  + (size_t)(bm + row) * K + kk * 64 + ch * 8;
            const __half* bg = Bm + (size_t)(bn + row) * K + kk * 64 + ch * 8;
            asm volatile("cp.async.cg.shared.global [%0], [%1], 16;" :: "r"(ab + sw), "l"(ag));
            asm volatile("cp.async.cg.shared.global [%0], [%1], 16;" :: "r"(bb + sw), "l"(bg));
        }
    };

    load_tiles(0, 0);
    asm volatile("cp.async.commit_group;");

    for (int it = 0; it < CH; ++it) {
        int st = it & 1;
        if (it + 1 < CH) {
            load_tiles((it + 1) & 1, it + 1);
            asm volatile("cp.async.commit_group;");
            asm volatile("cp.async.wait_group 1;");
        } else {
            asm volatile("cp.async.wait_group 0;");
        }
        __syncthreads();

        uint32_t aB = sb + st * STAGE;
        uint32_t bB = aB + 16384;
        #pragma unroll
        for (int kk8 = 0; kk8 < 8; kk8 += 2) {
            uint32_t ar[4][4], br[4][2];
            #pragma unroll
            for (int mf = 0; mf < 4; mf++) {
                int row = wm * 64 + mf * 16 + (lane & 15);
                int c = kk8 + (lane >> 4);
                uint32_t ad = aB + row * 128 + ((c ^ (row & 7)) << 4);
                asm volatile("ldmatrix.sync.aligned.m8n8.x4.shared.b16 {%0,%1,%2,%3}, [%4];"
                    : "=r"(ar[mf][0]), "=r"(ar[mf][1]), "=r"(ar[mf][2]), "=r"(ar[mf][3]) : "r"(ad));
            }
            #pragma unroll
            for (int nf = 0; nf < 4; nf++) {
                int nr = wn * 32 + nf * 8 + (lane & 7);
                int c = kk8 + ((lane >> 3) & 1);
                uint32_t bd = bB + nr * 128 + ((c ^ (nr & 7)) << 4);
                asm volatile("ldmatrix.sync.aligned.m8n8.x2.shared.b16 {%0,%1}, [%2];"
                    : "=r"(br[nf][0]), "=r"(br[nf][1]) : "r"(bd));
            }
            #pragma unroll
            for (int mf = 0; mf < 4; mf++)
                #pragma unroll
                for (int nf = 0; nf < 4; nf++) {
                    asm volatile(
                        "mma.sync.aligned.m16n8k16.row.col.f32.f16.f16.f32 "
                        "{%0,%1,%2,%3}, {%4,%5,%6,%7}, {%8,%9}, {%0,%1,%2,%3};"
                        : "+f"(acc[mf][nf][0]), "+f"(acc[mf][nf][1]),
                          "+f"(acc[mf][nf][2]), "+f"(acc[mf][nf][3])
                        : "r"(ar[mf][0]), "r"(ar[mf][1]), "r"(ar[mf][2]), "r"(ar[mf][3]),
                          "r"(br[nf][0]), "r"(br[nf][1]));
                }
        }
        __syncthreads();
    }

    #pragma unroll
    for (int mf = 0; mf < 4; mf++) {
        int r0 = bm + wm * 64 + mf * 16 + (lane >> 2);
        #pragma unroll
        for (int nf = 0; nf < 4; nf++) {
            int c0 = bn + wn * 32 + nf * 8 + (lane & 3) * 2;
            float* p0 = C + (size_t)r0 * ldc + c0;
            float* p1 = C + (size_t)(r0 + 8) * ldc + c0;
            p0[0] = acc[mf][nf][0]; p0[1] = acc[mf][nf][1];
            p1[0] = acc[mf][nf][2]; p1[1] = acc[mf][nf][3];
        }
    }
}

// ================= fp32 NT SGEMM 64x64 (small GEMMs) =================
template<bool RELU>
__global__ void __launch_bounds__(256) sgemm64(
    const float* __restrict__ A, const float* __restrict__ Bm,
    float* __restrict__ C, int M, int N, int K,
    int ldc, int n0, const float* __restrict__ bias)
{
    __shared__ float As[16][64];
    __shared__ float Bs[16][64];
    const int tid = threadIdx.x;
    const int bm = blockIdx.y * 64;
    const int bn = blockIdx.x * 64;
    const int tx = tid & 15;
    const int ty = tid >> 4;
    const int lr = tid >> 2;
    const int lc = (tid & 3) * 4;

    float acc[4][4];
    #pragma unroll
    for (int i = 0; i < 4; i++)
        #pragma unroll
        for (int j = 0; j < 4; j++) acc[i][j] = 0.f;

    const float* Aptr = A + (size_t)(bm + lr) * K + lc;
    const float* Bptr = Bm + (size_t)(bn + lr) * K + lc;

    for (int k0 = 0; k0 < K; k0 += 16) {
        float4 av = *(const float4*)(Aptr + k0);
        float4 bv = *(const float4*)(Bptr + k0);
        __syncthreads();
        As[lc + 0][lr] = av.x; As[lc + 1][lr] = av.y;
        As[lc + 2][lr] = av.z; As[lc + 3][lr] = av.w;
        Bs[lc + 0][lr] = bv.x; Bs[lc + 1][lr] = bv.y;
        Bs[lc + 2][lr] = bv.z; Bs[lc + 3][lr] = bv.w;
        __syncthreads();
        #pragma unroll
        for (int kk = 0; kk < 16; kk++) {
            float a[4], b[4];
            *(float4*)a = *(const float4*)&As[kk][ty * 4];
            *(float4*)b = *(const float4*)&Bs[kk][tx * 4];
            #pragma unroll
            for (int i = 0; i < 4; i++)
                #pragma unroll
                for (int j = 0; j < 4; j++)
                    acc[i][j] = fmaf(a[i], b[j], acc[i][j]);
        }
    }
    #pragma unroll
    for (int i = 0; i < 4; i++) {
        int row = bm + ty * 4 + i;
        #pragma unroll
        for (int j = 0; j < 4; j++) {
            int col = bn + tx * 4 + j;
            float v = acc[i][j];
            if (bias) v += bias[col];
            if (RELU) v = fmaxf(v, 0.f);
            C[(size_t)row * ldc + n0 + col] = v;
        }
    }
}

// ================= weight fp32 -> fp16 =================
__global__ void wconv(const float* __restrict__ W, __half* __restrict__ dst, int n)
{
    int idx = blockIdx.x * blockDim.x + threadIdx.x;
    if (idx < n) dst[idx] = __float2half_rn(W[idx]);
}

// ================= builders =================
__global__ void build_x1h(const float* __restrict__ enc_row, const float* __restrict__ enc_col,
                          const float* __restrict__ clockv, const float* __restrict__ endt,
                          const int* __restrict__ loc_id, const int* __restrict__ robot,
                          const int* __restrict__ hold, const int* __restrict__ stage,
                          const float* __restrict__ Wdyn)
{
    int blk = blockIdx.x;
    int b = blk >> 5, p = blk & 31;
    float ck = clockv[b];
    float et = endt[b * PP + p];
    float remain = fmaxf(et - ck, 0.f) * INV_NORM;
    int st = stage[b * PP + p] - 1;
    int hw = hold[b * PP + p];
    __half* row = g_X1h + (size_t)blk * K3;
    const float* cs = enc_col + ((size_t)b * NS_ + st) * DD;
    const float* ws = (hw >= 0) ? enc_row + ((size_t)b * NW_ + hw) * DD : nullptr;
    for (int d = threadIdx.x; d < DD; d += blockDim.x) {
        row[d] = __float2half_rn(cs[d]);
        row[DD + d] = __float2half_rn(ws ? ws[d] : 0.f);
        row[2 * DD + d] = __float2half_rn(remain * Wdyn[2 * d]);
    }
    if (threadIdx.x == 0) {
        int rb = robot[b];
        float pk = ck + 3.f * (loc_id[b * PP + p] != rb);
        g_dpm[blk] = (fmaxf(et, pk) + 9.f - ck) * INV_NORM;
        if (p == 0) g_dll[b] = (3.f * (rb != 0) + 9.f) * INV_NORM;
    }
}

__global__ void build_g12(const float* __restrict__ enc_row,
                          const int* __restrict__ ll1, const int* __restrict__ ll2)
{
    int b = blockIdx.x;
    const float* r1 = enc_row + ((size_t)b * NW_ + ll1[b]) * DD;
    const float* r2 = enc_row + ((size_t)b * NW_ + ll2[b]) * DD;
    float* dst = g_g12 + (size_t)b * 2 * DD;
    for (int d = threadIdx.x; d < DD; d += blockDim.x) {
        dst[d] = r1[d];
        dst[DD + d] = r2[d];
    }
}

__global__ void build_actionh(const float* __restrict__ enc_row,
                              const int* __restrict__ ll1, const int* __restrict__ ll2,
                              const int* __restrict__ hold, const float* __restrict__ Wtime)
{
    int blk = blockIdx.x;
    int b = blk / AA, j = blk - b * AA;
    __half* row = g_acth + (size_t)blk * K3;
    if (j < 2) {
        int rec = (j == 0) ? ll1[b] : ll2[b];
        const float* g = enc_row + ((size_t)b * NW_ + rec) * DD;
        float dl = g_dll[b];
        for (int d = threadIdx.x; d < DD; d += blockDim.x) {
            row[d] = __float2half_rn(0.f);
            row[DD + d] = __float2half_rn(g[d]);
            row[2 * DD + d] = __float2half_rn(dl * Wtime[d]);
        }
    } else {
        int p = j - 2;
        int hw = hold[b * PP + p];
        const float* ws = (hw >= 0) ? enc_row + ((size_t)b * NW_ + hw) * DD : nullptr;
        const float* pe = g_pm_emb + (size_t)(b * PP + p) * DD;
        float dp = g_dpm[b * PP + p];
        for (int d = threadIdx.x; d < DD; d += blockDim.x) {
            row[d] = __float2half_rn(pe[d]);
            row[DD + d] = __float2half_rn(ws ? ws[d] : 0.f);
            row[2 * DD + d] = __float2half_rn(dp * Wtime[d]);
        }
    }
}

__global__ void pm_mean_rb(const int* __restrict__ robot)
{
    int b = blockIdx.x;
    int rb = robot[b];
    for (int d = threadIdx.x; d < DD; d += blockDim.x) {
        float s = 0.f;
        #pragma unroll 8
        for (int p = 0; p < PP; p++)
            s += g_pm_emb[((size_t)(b * PP + p)) * DD + d];
        g_pmmean[(size_t)b * DD + d] = s * (1.f / PP);
        g_pmrb[(size_t)b * DD + d] = g_pm_emb[((size_t)(b * PP + rb)) * DD + d];
    }
}

// ================= attention over g_KVS [K|V|SHK] (ld=1536) =================
__global__ void attention(const void* __restrict__ mask)
{
    int b = blockIdx.x;
    int h = threadIdx.x >> 5, lane = threadIdx.x & 31;
    __shared__ float ps[HH][AA + 2];
    float q = g_q[(size_t)b * DD + h * QKD + lane];
    const float scale = rsqrtf((float)QKD);
    for (int j = 0; j < AA; j++) {
        float kv = g_KVS[((size_t)(b * AA + j)) * (3 * DD) + h * QKD + lane];
        float s = q * kv;
        #pragma unroll
        for (int o = 16; o > 0; o >>= 1) s += __shfl_xor_sync(0xffffffffu, s, o);
        if (lane == 0) ps[h][j] = s * scale + (mask_at(mask, b * AA + j) ? 0.f : -1e10f);
    }
    __syncwarp();
    float m = -INFINITY;
    for (int j = 0; j < AA; j++) m = fmaxf(m, ps[h][j]);
    float sum = 0.f;
    for (int j = 0; j < AA; j++) sum += expf(ps[h][j] - m);
    float inv = 1.f / sum;
    float o = 0.f;
    for (int j = 0; j < AA; j++)
        o += expf(ps[h][j] - m) * inv * g_KVS[((size_t)(b * AA + j)) * (3 * DD) + DD + h * QKD + lane];
    g_attout[(size_t)b * DD + h * QKD + lane] = o;
}

__global__ void final_kernel(const void* __restrict__ mask, float* __restrict__ out)
{
    int b = blockIdx.x;
    int w = threadIdx.x >> 5, lane = threadIdx.x & 31;
    __shared__ float sc[AA];
    const float* mh = g_mh + (size_t)b * DD;
    const float scale = rsqrtf((float)DD);
    for (int a = w; a < AA; a += 8) {
        const float* s = g_KVS + ((size_t)(b * AA + a)) * (3 * DD) + 2 * DD;
        float acc = 0.f;
        for (int d = lane; d < DD; d += 32) acc = fmaf(mh[d], s[d], acc);
        #pragma unroll
        for (int o = 16; o > 0; o >>= 1) acc += __shfl_xor_sync(0xffffffffu, acc, o);
        if (lane == 0)
            sc[a] = 10.f * tanhf(acc * scale) + (mask_at(mask, b * AA + a) ? 0.f : -1e10f);
    }
    __syncthreads();
    if (threadIdx.x < AA) {
        float m = -INFINITY;
        for (int j = 0; j < AA; j++) m = fmaxf(m, sc[j]);
        float sum = 0.f;
        for (int j = 0; j < AA; j++) sum += expf(sc[j] - m);
        out[b * AA + threadIdx.x] = expf(sc[threadIdx.x] - m) / sum;
    }
}

// ================= launch =================
static inline void gemm_s(const float* A, const float* Bm, float* C,
                          int M, int N, int K, int ldc, int n0,
                          const float* bias, bool relu)
{
    dim3 grid(N / 64, M / 64);
    if (relu) sgemm64<true><<<grid, 256>>>(A, Bm, C, M, N, K, ldc, n0, bias);
    else      sgemm64<false><<<grid, 256>>>(A, Bm, C, M, N, K, ldc, n0, bias);
}

extern "C" void kernel_launch(void* const* d_in, const int* in_sizes, int n_in,
                              void* d_out, int out_size)
{
    const float* enc_row = (const float*)d_in[0];
    const float* enc_col = (const float*)d_in[1];
    const float* clockv  = (const float*)d_in[2];
    const float* endt    = (const float*)d_in[3];
    const int* loc_id    = (const int*)d_in[4];
    const int* robot     = (const int*)d_in[5];
    const int* hold      = (const int*)d_in[6];
    const int* stage     = (const int*)d_in[7];
    const int* ll1       = (const int*)d_in[8];
    const int* ll2       = (const int*)d_in[9];
    const void* mask     = d_in[10];
    const float* W_dyn   = (const float*)d_in[11];
    const float* W_pmcat = (const float*)d_in[12];
    const float* W_time  = (const float*)d_in[13];
    const float* W_llctx = (const float*)d_in[14];
    const float* W_pmctx = (const float*)d_in[15];
    const float* W_rbctx = (const float*)d_in[16];
    const float* W_cc1   = (const float*)d_in[17];
    const float* b_cc1   = (const float*)d_in[18];
    const float* W_cc2   = (const float*)d_in[19];
    const float* b_cc2   = (const float*)d_in[20];
    const float* Wq      = (const float*)d_in[21];
    const float* Wk      = (const float*)d_in[22];
    const float* Wv      = (const float*)d_in[23];
    const float* Wshk    = (const float*)d_in[24];
    const float* W_mhc   = (const float*)d_in[25];
    const float* b_mhc   = (const float*)d_in[26];
    float* out = (float*)d_out;

    __half *X1h, *acth, *Wpmh, *Wkvsh;
    float *pm_emb, *KVS, *g12, *pmmean, *pmrb, *ctx, *h1, *ctxt, *qm, *attout, *mh;
    cudaGetSymbolAddress((void**)&X1h, g_X1h);
    cudaGetSymbolAddress((void**)&acth, g_acth);
    cudaGetSymbolAddress((void**)&Wpmh, g_Wpmh);
    cudaGetSymbolAddress((void**)&Wkvsh, g_Wkvsh);
    cudaGetSymbolAddress((void**)&pm_emb, g_pm_emb);
    cudaGetSymbolAddress((void**)&KVS, g_KVS);
    cudaGetSymbolAddress((void**)&g12, g_g12);
    cudaGetSymbolAddress((void**)&pmmean, g_pmmean);
    cudaGetSymbolAddress((void**)&pmrb, g_pmrb);
    cudaGetSymbolAddress((void**)&ctx, g_ctx);
    cudaGetSymbolAddress((void**)&h1, g_h1);
    cudaGetSymbolAddress((void**)&ctxt, g_ctxt);
    cudaGetSymbolAddress((void**)&qm, g_q);
    cudaGetSymbolAddress((void**)&attout, g_attout);
    cudaGetSymbolAddress((void**)&mh, g_mh);

    const int MMA_SMEM = 65536;  // 2 stages x 32KB
    cudaFuncSetAttribute(gemm_mma, cudaFuncAttributeMaxDynamicSharedMemorySize, MMA_SMEM);

    // 0. mask dtype sniff
    detect_mask<<<1, 256>>>((const unsigned int*)mask);

    // 1. builders + weight converts
    build_x1h<<<BB * PP, 128>>>(enc_row, enc_col, clockv, endt, loc_id, robot, hold, stage, W_dyn);
    build_g12<<<BB, 256>>>(enc_row, ll1, ll2);
    {
        int n = DD * K3, thr = 256, blocks = (n + thr - 1) / thr;
        wconv<<<blocks, thr>>>(W_pmcat, Wpmh, n);
        wconv<<<blocks, thr>>>(Wk,   Wkvsh, n);
        wconv<<<blocks, thr>>>(Wv,   Wkvsh + (size_t)DD * K3, n);
        wconv<<<blocks, thr>>>(Wshk, Wkvsh + (size_t)2 * DD * K3, n);
    }

    // 2. pm_emb = X1 @ W_pmcat^T  (HMMA fp16 single-pass, 16384x512x1536)
    gemm_mma<<<dim3(DD / 128, BB * PP / 128), 256, MMA_SMEM>>>(X1h, Wpmh, pm_emb, BB * PP, K3, DD);

    // 3. action + context gathers
    build_actionh<<<BB * AA, 128>>>(enc_row, ll1, ll2, hold, W_time);
    pm_mean_rb<<<BB, 256>>>(robot);

    // 4. ctx = [ll_ctx | pm_ctx | rb_ctx]
    gemm_s(g12, W_llctx, ctx, BB, DD, 2 * DD, 3 * DD, 0, nullptr, false);
    gemm_s(pmmean, W_pmctx, ctx, BB, DD, DD, 3 * DD, DD, nullptr, false);
    gemm_s(pmrb, W_rbctx, ctx, BB, DD, DD, 3 * DD, 2 * DD, nullptr, false);

    // 5. context MLP + q
    gemm_s(ctx, W_cc1, h1, BB, DD, 3 * DD, DD, 0, b_cc1, true);
    gemm_s(h1, W_cc2, ctxt, BB, DD, DD, DD, 0, b_cc2, false);
    gemm_s(ctxt, Wq, qm, BB, DD, DD, DD, 0, nullptr, false);

    // 6. fused K|V|SHK projection  (HMMA fp16 single-pass, 17408x1536x1536)
    gemm_mma<<<dim3(3 * DD / 128, BB * AA / 128), 256, MMA_SMEM>>>(acth, Wkvsh, KVS, BB * AA, K3, 3 * DD);

    // 7. attention -> mh -> final softmax
    attention<<<BB, HH * 32>>>(mask);
    gemm_s(attout, W_mhc, mh, BB, DD, DD, DD, 0, b_mhc, false);
    final_kernel<<<BB, 256>>>(mask, out);
}

// round 13
// speedup vs baseline: 6.0071x; 1.2665x over previous
#include <cuda_runtime.h>
#include <cuda_fp16.h>
#include <math.h>
#include <stdint.h>

#define BB 512
#define NW_ 256
#define NS_ 8
#define PP 32
#define DD 512
#define HH 16
#define QKD 32
#define AA 34
#define INV_NORM (1.0f/300.0f)
#define K3 1536

__device__ __forceinline__ uint32_t smem_u32(const void* p) {
    uint32_t a;
    asm("{ .reg .u64 t; cvta.to.shared.u64 t, %1; cvt.u32.u64 %0, t; }" : "=r"(a) : "l"(p));
    return a;
}

// ================= scratch =================
__device__ __align__(1024) __half g_X1h[(size_t)BB*PP*K3];
__device__ __align__(1024) __half g_acth[(size_t)BB*AA*K3];
__device__ __align__(1024) __half g_Wpmh[(size_t)DD*K3];
__device__ __align__(1024) __half g_Wkvsh[(size_t)3*DD*K3];
__device__ __align__(128) float g_pm_emb[(size_t)BB*PP*DD];
__device__ __align__(128) float g_KVS[(size_t)BB*AA*3*DD];
__device__ __align__(128) float g_g12[(size_t)BB*2*DD];
__device__ __align__(128) float g_pmmean[(size_t)BB*DD];
__device__ __align__(128) float g_pmrb[(size_t)BB*DD];
__device__ __align__(128) float g_ctx[(size_t)BB*3*DD];
__device__ __align__(128) float g_h1[(size_t)BB*DD];
__device__ __align__(128) float g_ctxt[(size_t)BB*DD];
__device__ __align__(128) float g_q[(size_t)BB*DD];
__device__ __align__(128) float g_attout[(size_t)BB*DD];
__device__ __align__(128) float g_mh[(size_t)BB*DD];
__device__ __align__(128) float g_dll[BB];
__device__ __align__(128) float g_dpm[BB*PP];
__device__ int g_mask_wordmode;

__device__ __forceinline__ bool mask_at(const void* m, int i)
{
    if (g_mask_wordmode) return ((const unsigned int*)m)[i] != 0u;
    return ((const unsigned char*)m)[i] != 0u;
}

// ================= merged builder: x1 + g12 + mask-detect =================
__global__ void build_all(const float* __restrict__ enc_row, const float* __restrict__ enc_col,
                          const float* __restrict__ clockv, const float* __restrict__ endt,
                          const int* __restrict__ loc_id, const int* __restrict__ robot,
                          const int* __restrict__ hold, const int* __restrict__ stage,
                          const float* __restrict__ Wdyn,
                          const int* __restrict__ ll1, const int* __restrict__ ll2,
                          const unsigned int* __restrict__ mw)
{
    int blk = blockIdx.x;
    if (blk < BB * PP) {
        int b = blk >> 5, p = blk & 31;
        float ck = clockv[b];
        float et = endt[b * PP + p];
        float remain = fmaxf(et - ck, 0.f) * INV_NORM;
        int st = stage[b * PP + p] - 1;
        int hw = hold[b * PP + p];
        __half* row = g_X1h + (size_t)blk * K3;
        const float* cs = enc_col + ((size_t)b * NS_ + st) * DD;
        const float* ws = (hw >= 0) ? enc_row + ((size_t)b * NW_ + hw) * DD : nullptr;
        for (int d = threadIdx.x; d < DD; d += blockDim.x) {
            row[d] = __float2half_rn(cs[d]);
            row[DD + d] = __float2half_rn(ws ? ws[d] : 0.f);
            row[2 * DD + d] = __float2half_rn(remain * Wdyn[2 * d]);
        }
        if (threadIdx.x == 0) {
            int rb = robot[b];
            float pk = ck + 3.f * (loc_id[b * PP + p] != rb);
            g_dpm[blk] = (fmaxf(et, pk) + 9.f - ck) * INV_NORM;
            if (p == 0) g_dll[b] = (3.f * (rb != 0) + 9.f) * INV_NORM;
        }
    } else if (blk < BB * PP + BB) {
        int b = blk - BB * PP;
        const float* r1 = enc_row + ((size_t)b * NW_ + ll1[b]) * DD;
        const float* r2 = enc_row + ((size_t)b * NW_ + ll2[b]) * DD;
        float* dst = g_g12 + (size_t)b * 2 * DD;
        for (int d = threadIdx.x; d < DD; d += blockDim.x) {
            dst[d] = r1[d];
            dst[DD + d] = r2[d];
        }
    } else {
        __shared__ int bad;
        if (threadIdx.x == 0) bad = 0;
        __syncthreads();
        for (int i = threadIdx.x; i < (BB * AA) / 4; i += blockDim.x) {
            unsigned int w = mw[i];
            if (w != 0u && w != 1u && w != 0x3F800000u) atomicExch(&bad, 1);
        }
        __syncthreads();
        if (threadIdx.x == 0) g_mask_wordmode = !bad;
    }
}

// ================= merged weight convert (4 matrices) =================
__global__ void wconv_all(const float* __restrict__ Wpm, const float* __restrict__ Wk,
                          const float* __restrict__ Wv, const float* __restrict__ Wshk)
{
    const int n = DD * K3;
    int idx = blockIdx.x * blockDim.x + threadIdx.x;
    if (idx >= 4 * n) return;
    int which = idx / n, off = idx - which * n;
    const float* src = (which == 0) ? Wpm : (which == 1) ? Wk : (which == 2) ? Wv : Wshk;
    __half* dst = (which == 0) ? g_Wpmh : g_Wkvsh + (size_t)(which - 1) * n;
    dst[off] = __float2half_rn(src[off]);
}

// ================= fp16 NT GEMM via mma.sync =================
__global__ void __launch_bounds__(256) gemm_mma(
    const __half* __restrict__ A, const __half* __restrict__ Bm,
    float* __restrict__ C, int M, int K, int ldc)
{
    extern __shared__ char smem[];
    const uint32_t sb = smem_u32(smem);
    const int tid = threadIdx.x;
    const int lane = tid & 31;
    const int wid = tid >> 5;
    const int wm = wid >> 2;
    const int wn = wid & 3;
    const int bm = blockIdx.y * 128;
    const int bn = blockIdx.x * 128;
    const uint32_t STAGE = 32768;
    const int CH = K / 64;

    float acc[4][4][4];
    #pragma unroll
    for (int i = 0; i < 4; i++)
        #pragma unroll
        for (int j = 0; j < 4; j++)
            #pragma unroll
            for (int r = 0; r < 4; r++) acc[i][j][r] = 0.f;

    auto load_tiles = [&](int st, int kk) {
        uint32_t ab = sb + st * STAGE;
        uint32_t bb = ab + 16384;
        #pragma unroll
        for (int i = 0; i < 4; i++) {
            int idx = tid + i * 256;
            int row = idx >> 3, ch = idx & 7;
            uint32_t sw = (uint32_t)(row * 128 + ((ch ^ (row & 7)) << 4));
            const __half* ag = A  + (size_t)(bm + row) * K + kk * 64 + ch * 8;
            const __half* bg = Bm + (size_t)(bn + row) * K + kk * 64 + ch * 8;
            asm volatile("cp.async.cg.shared.global [%0], [%1], 16;" :: "r"(ab + sw), "l"(ag));
            asm volatile("cp.async.cg.shared.global [%0], [%1], 16;" :: "r"(bb + sw), "l"(bg));
        }
    };

    load_tiles(0, 0);
    asm volatile("cp.async.commit_group;");

    for (int it = 0; it < CH; ++it) {
        int st = it & 1;
        if (it + 1 < CH) {
            load_tiles((it + 1) & 1, it + 1);
            asm volatile("cp.async.commit_group;");
            asm volatile("cp.async.wait_group 1;");
        } else {
            asm volatile("cp.async.wait_group 0;");
        }
        __syncthreads();

        uint32_t aB = sb + st * STAGE;
        uint32_t bB = aB + 16384;
        #pragma unroll
        for (int kk8 = 0; kk8 < 8; kk8 += 2) {
            uint32_t ar[4][4], br[4][2];
            #pragma unroll
            for (int mf = 0; mf < 4; mf++) {
                int row = wm * 64 + mf * 16 + (lane & 15);
                int c = kk8 + (lane >> 4);
                uint32_t ad = aB + row * 128 + ((c ^ (row & 7)) << 4);
                asm volatile("ldmatrix.sync.aligned.m8n8.x4.shared.b16 {%0,%1,%2,%3}, [%4];"
                    : "=r"(ar[mf][0]), "=r"(ar[mf][1]), "=r"(ar[mf][2]), "=r"(ar[mf][3]) : "r"(ad));
            }
            // B fragments: one ldmatrix.x4 covers two adjacent nf slices (16 n-rows x 16 k)
            #pragma unroll
            for (int nfp = 0; nfp < 2; nfp++) {
                int nr = wn * 32 + nfp * 16 + ((lane & 7) | ((lane >> 4) << 3));
                int c = kk8 + ((lane >> 3) & 1);
                uint32_t bd = bB + nr * 128 + ((c ^ (nr & 7)) << 4);
                asm volatile("ldmatrix.sync.aligned.m8n8.x4.shared.b16 {%0,%1,%2,%3}, [%4];"
                    : "=r"(br[2 * nfp][0]), "=r"(br[2 * nfp][1]),
                      "=r"(br[2 * nfp + 1][0]), "=r"(br[2 * nfp + 1][1]) : "r"(bd));
            }
            #pragma unroll
            for (int mf = 0; mf < 4; mf++)
                #pragma unroll
                for (int nf = 0; nf < 4; nf++) {
                    asm volatile(
                        "mma.sync.aligned.m16n8k16.row.col.f32.f16.f16.f32 "
                        "{%0,%1,%2,%3}, {%4,%5,%6,%7}, {%8,%9}, {%0,%1,%2,%3};"
                        : "+f"(acc[mf][nf][0]), "+f"(acc[mf][nf][1]),
                          "+f"(acc[mf][nf][2]), "+f"(acc[mf][nf][3])
                        : "r"(ar[mf][0]), "r"(ar[mf][1]), "r"(ar[mf][2]), "r"(ar[mf][3]),
                          "r"(br[nf][0]), "r"(br[nf][1]));
                }
        }
        __syncthreads();
    }

    #pragma unroll
    for (int mf = 0; mf < 4; mf++) {
        int r0 = bm + wm * 64 + mf * 16 + (lane >> 2);
        #pragma unroll
        for (int nf = 0; nf < 4; nf++) {
            int c0 = bn + wn * 32 + nf * 8 + (lane & 3) * 2;
            float* p0 = C + (size_t)r0 * ldc + c0;
            float* p1 = C + (size_t)(r0 + 8) * ldc + c0;
            p0[0] = acc[mf][nf][0]; p0[1] = acc[mf][nf][1];
            p1[0] = acc[mf][nf][2]; p1[1] = acc[mf][nf][3];
        }
    }
}

// ================= fp32 NT SGEMM 64x64 =================
template<bool RELU>
__device__ __forceinline__ void sgemm64_body(
    const float* __restrict__ A, const float* __restrict__ Bm,
    float* __restrict__ C, int K, int ldc, int n0, const float* __restrict__ bias,
    int bm, int bn)
{
    __shared__ float As[16][64];
    __shared__ float Bs[16][64];
    const int tid = threadIdx.x;
    const int tx = tid & 15;
    const int ty = tid >> 4;
    const int lr = tid >> 2;
    const int lc = (tid & 3) * 4;

    float acc[4][4];
    #pragma unroll
    for (int i = 0; i < 4; i++)
        #pragma unroll
        for (int j = 0; j < 4; j++) acc[i][j] = 0.f;

    const float* Aptr = A + (size_t)(bm + lr) * K + lc;
    const float* Bptr = Bm + (size_t)(bn + lr) * K + lc;

    for (int k0 = 0; k0 < K; k0 += 16) {
        float4 av = *(const float4*)(Aptr + k0);
        float4 bv = *(const float4*)(Bptr + k0);
        __syncthreads();
        As[lc + 0][lr] = av.x; As[lc + 1][lr] = av.y;
        As[lc + 2][lr] = av.z; As[lc + 3][lr] = av.w;
        Bs[lc + 0][lr] = bv.x; Bs[lc + 1][lr] = bv.y;
        Bs[lc + 2][lr] = bv.z; Bs[lc + 3][lr] = bv.w;
        __syncthreads();
        #pragma unroll
        for (int kk = 0; kk < 16; kk++) {
            float a[4], b[4];
            *(float4*)a = *(const float4*)&As[kk][ty * 4];
            *(float4*)b = *(const float4*)&Bs[kk][tx * 4];
            #pragma unroll
            for (int i = 0; i < 4; i++)
                #pragma unroll
                for (int j = 0; j < 4; j++)
                    acc[i][j] = fmaf(a[i], b[j], acc[i][j]);
        }
    }
    #pragma unroll
    for (int i = 0; i < 4; i++) {
        int row = bm + ty * 4 + i;
        #pragma unroll
        for (int j = 0; j < 4; j++) {
            int col = bn + tx * 4 + j;
            float v = acc[i][j];
            if (bias) v += bias[col];
            if (RELU) v = fmaxf(v, 0.f);
            C[(size_t)row * ldc + n0 + col] = v;
        }
    }
}

template<bool RELU>
__global__ void __launch_bounds__(256) sgemm64(
    const float* __restrict__ A, const float* __restrict__ Bm,
    float* __restrict__ C, int K, int ldc, int n0, const float* __restrict__ bias)
{
    sgemm64_body<RELU>(A, Bm, C, K, ldc, n0, bias, blockIdx.y * 64, blockIdx.x * 64);
}

// z-batched ctx GEMM: z=0 llctx (K=2D), z=1 pmctx (K=D), z=2 rbctx (K=D)
__global__ void __launch_bounds__(256) ctx3_gemm(
    const float* __restrict__ W0, const float* __restrict__ W1, const float* __restrict__ W2)
{
    int z = blockIdx.z;
    const float* A = (z == 0) ? g_g12 : (z == 1) ? g_pmmean : g_pmrb;
    const float* W = (z == 0) ? W0 : (z == 1) ? W1 : W2;
    int K = (z == 0) ? 2 * DD : DD;
    sgemm64_body<false>(A, W, g_ctx, K, 3 * DD, z * DD, nullptr,
                        blockIdx.y * 64, blockIdx.x * 64);
}

// ================= action builder =================
__global__ void build_actionh(const float* __restrict__ enc_row,
                              const int* __restrict__ ll1, const int* __restrict__ ll2,
                              const int* __restrict__ hold, const float* __restrict__ Wtime)
{
    int blk = blockIdx.x;
    int b = blk / AA, j = blk - b * AA;
    __half* row = g_acth + (size_t)blk * K3;
    if (j < 2) {
        int rec = (j == 0) ? ll1[b] : ll2[b];
        const float* g = enc_row + ((size_t)b * NW_ + rec) * DD;
        float dl = g_dll[b];
        for (int d = threadIdx.x; d < DD; d += blockDim.x) {
            row[d] = __float2half_rn(0.f);
            row[DD + d] = __float2half_rn(g[d]);
            row[2 * DD + d] = __float2half_rn(dl * Wtime[d]);
        }
    } else {
        int p = j - 2;
        int hw = hold[b * PP + p];
        const float* ws = (hw >= 0) ? enc_row + ((size_t)b * NW_ + hw) * DD : nullptr;
        const float* pe = g_pm_emb + (size_t)(b * PP + p) * DD;
        float dp = g_dpm[b * PP + p];
        for (int d = threadIdx.x; d < DD; d += blockDim.x) {
            row[d] = __float2half_rn(pe[d]);
            row[DD + d] = __float2half_rn(ws ? ws[d] : 0.f);
            row[2 * DD + d] = __float2half_rn(dp * Wtime[d]);
        }
    }
}

__global__ void pm_mean_rb(const int* __restrict__ robot)
{
    int b = blockIdx.x;
    int rb = robot[b];
    for (int d = threadIdx.x; d < DD; d += blockDim.x) {
        float s = 0.f;
        #pragma unroll 8
        for (int p = 0; p < PP; p++)
            s += g_pm_emb[((size_t)(b * PP + p)) * DD + d];
        g_pmmean[(size_t)b * DD + d] = s * (1.f / PP);
        g_pmrb[(size_t)b * DD + d] = g_pm_emb[((size_t)(b * PP + rb)) * DD + d];
    }
}

// ================= attention =================
__global__ void attention(const void* __restrict__ mask)
{
    int b = blockIdx.x;
    int h = threadIdx.x >> 5, lane = threadIdx.x & 31;
    __shared__ float ps[HH][AA + 2];
    float q = g_q[(size_t)b * DD + h * QKD + lane];
    const float scale = rsqrtf((float)QKD);
    for (int j = 0; j < AA; j++) {
        float kv = g_KVS[((size_t)(b * AA + j)) * (3 * DD) + h * QKD + lane];
        float s = q * kv;
        #pragma unroll
        for (int o = 16; o > 0; o >>= 1) s += __shfl_xor_sync(0xffffffffu, s, o);
        if (lane == 0) ps[h][j] = s * scale + (mask_at(mask, b * AA + j) ? 0.f : -1e10f);
    }
    __syncwarp();
    float m = -INFINITY;
    for (int j = 0; j < AA; j++) m = fmaxf(m, ps[h][j]);
    float sum = 0.f;
    for (int j = 0; j < AA; j++) sum += expf(ps[h][j] - m);
    float inv = 1.f / sum;
    float o = 0.f;
    for (int j = 0; j < AA; j++)
        o += expf(ps[h][j] - m) * inv * g_KVS[((size_t)(b * AA + j)) * (3 * DD) + DD + h * QKD + lane];
    g_attout[(size_t)b * DD + h * QKD + lane] = o;
}

__global__ void final_kernel(const void* __restrict__ mask, float* __restrict__ out)
{
    int b = blockIdx.x;
    int w = threadIdx.x >> 5, lane = threadIdx.x & 31;
    __shared__ float sc[AA];
    const float* mh = g_mh + (size_t)b * DD;
    const float scale = rsqrtf((float)DD);
    for (int a = w; a < AA; a += 8) {
        const float* s = g_KVS + ((size_t)(b * AA + a)) * (3 * DD) + 2 * DD;
        float acc = 0.f;
        for (int d = lane; d < DD; d += 32) acc = fmaf(mh[d], s[d], acc);
        #pragma unroll
        for (int o = 16; o > 0; o >>= 1) acc += __shfl_xor_sync(0xffffffffu, acc, o);
        if (lane == 0)
            sc[a] = 10.f * tanhf(acc * scale) + (mask_at(mask, b * AA + a) ? 0.f : -1e10f);
    }
    __syncthreads();
    if (threadIdx.x < AA) {
        float m = -INFINITY;
        for (int j = 0; j < AA; j++) m = fmaxf(m, sc[j]);
        float sum = 0.f;
        for (int j = 0; j < AA; j++) sum += expf(sc[j] - m);
        out[b * AA + threadIdx.x] = expf(sc[threadIdx.x] - m) / sum;
    }
}

// ================= launch =================
extern "C" void kernel_launch(void* const* d_in, const int* in_sizes, int n_in,
                              void* d_out, int out_size)
{
    const float* enc_row = (const float*)d_in[0];
    const float* enc_col = (const float*)d_in[1];
    const float* clockv  = (const float*)d_in[2];
    const float* endt    = (const float*)d_in[3];
    const int* loc_id    = (const int*)d_in[4];
    const int* robot     = (const int*)d_in[5];
    const int* hold      = (const int*)d_in[6];
    const int* stage     = (const int*)d_in[7];
    const int* ll1       = (const int*)d_in[8];
    const int* ll2       = (const int*)d_in[9];
    const void* mask     = d_in[10];
    const float* W_dyn   = (const float*)d_in[11];
    const float* W_pmcat = (const float*)d_in[12];
    const float* W_time  = (const float*)d_in[13];
    const float* W_llctx = (const float*)d_in[14];
    const float* W_pmctx = (const float*)d_in[15];
    const float* W_rbctx = (const float*)d_in[16];
    const float* W_cc1   = (const float*)d_in[17];
    const float* b_cc1   = (const float*)d_in[18];
    const float* W_cc2   = (const float*)d_in[19];
    const float* b_cc2   = (const float*)d_in[20];
    const float* Wq      = (const float*)d_in[21];
    const float* Wk      = (const float*)d_in[22];
    const float* Wv      = (const float*)d_in[23];
    const float* Wshk    = (const float*)d_in[24];
    const float* W_mhc   = (const float*)d_in[25];
    const float* b_mhc   = (const float*)d_in[26];
    float* out = (float*)d_out;

    __half *X1h, *acth, *Wpmh, *Wkvsh;
    float *pm_emb, *KVS, *g12, *pmmean, *pmrb, *ctx, *h1, *ctxt, *qm, *attout, *mh;
    cudaGetSymbolAddress((void**)&X1h, g_X1h);
    cudaGetSymbolAddress((void**)&acth, g_acth);
    cudaGetSymbolAddress((void**)&Wpmh, g_Wpmh);
    cudaGetSymbolAddress((void**)&Wkvsh, g_Wkvsh);
    cudaGetSymbolAddress((void**)&pm_emb, g_pm_emb);
    cudaGetSymbolAddress((void**)&KVS, g_KVS);
    cudaGetSymbolAddress((void**)&g12, g_g12);
    cudaGetSymbolAddress((void**)&pmmean, g_pmmean);
    cudaGetSymbolAddress((void**)&pmrb, g_pmrb);
    cudaGetSymbolAddress((void**)&ctx, g_ctx);
    cudaGetSymbolAddress((void**)&h1, g_h1);
    cudaGetSymbolAddress((void**)&ctxt, g_ctxt);
    cudaGetSymbolAddress((void**)&qm, g_q);
    cudaGetSymbolAddress((void**)&attout, g_attout);
    cudaGetSymbolAddress((void**)&mh, g_mh);

    static cudaStream_t s1 = nullptr;
    static cudaEvent_t eA = nullptr, eB = nullptr;
    if (!s1) {
        cudaStreamCreateWithFlags(&s1, cudaStreamNonBlocking);
        cudaEventCreateWithFlags(&eA, cudaEventDisableTiming);
        cudaEventCreateWithFlags(&eB, cudaEventDisableTiming);
    }

    const int MMA_SMEM = 65536;
    cudaFuncSetAttribute(gemm_mma, cudaFuncAttributeMaxDynamicSharedMemorySize, MMA_SMEM);

    // --- stream 0: builders -> GEMM1 ---
    build_all<<<BB * PP + BB + 1, 128>>>(enc_row, enc_col, clockv, endt, loc_id, robot,
                                         hold, stage, W_dyn, ll1, ll2,
                                         (const unsigned int*)mask);
    wconv_all<<<(4 * DD * K3 + 255) / 256, 256>>>(W_pmcat, Wk, Wv, Wshk);
    gemm_mma<<<dim3(DD / 128, BB * PP / 128), 256, MMA_SMEM>>>(X1h, Wpmh, pm_emb, BB * PP, K3, DD);
    cudaEventRecord(eA, 0);

    // --- stream 1 (branch B): pm_mean -> ctx -> cc1 -> cc2 -> q ---
    cudaStreamWaitEvent(s1, eA, 0);
    pm_mean_rb<<<BB, 256, 0, s1>>>(robot);
    ctx3_gemm<<<dim3(DD / 64, BB / 64, 3), 256, 0, s1>>>(W_llctx, W_pmctx, W_rbctx);
    sgemm64<true><<<dim3(DD / 64, BB / 64), 256, 0, s1>>>(ctx, W_cc1, h1, 3 * DD, DD, 0, b_cc1);
    sgemm64<false><<<dim3(DD / 64, BB / 64), 256, 0, s1>>>(h1, W_cc2, ctxt, DD, DD, 0, b_cc2);
    sgemm64<false><<<dim3(DD / 64, BB / 64), 256, 0, s1>>>(ctxt, Wq, qm, DD, DD, 0, nullptr);
    cudaEventRecord(eB, s1);

    // --- stream 0 (branch A): action -> KVS GEMM ---
    build_actionh<<<BB * AA, 128>>>(enc_row, ll1, ll2, hold, W_time);
    gemm_mma<<<dim3(3 * DD / 128, BB * AA / 128), 256, MMA_SMEM>>>(acth, Wkvsh, KVS, BB * AA, K3, 3 * DD);

    // --- join, then attention tail on stream 0 ---
    cudaStreamWaitEvent(0, eB, 0);
    attention<<<BB, HH * 32>>>(mask);
    sgemm64<false><<<dim3(DD / 64, BB / 64), 256>>>(attout, W_mhc, mh, DD, DD, 0, b_mhc);
    final_kernel<<<BB, 256>>>(mask, out);
}

// round 17
// speedup vs baseline: 6.7585x; 1.1251x over previous
#include <cuda_runtime.h>
#include <cuda_fp16.h>
#include <math.h>
#include <stdint.h>

#define BB 512
#define NW_ 256
#define NS_ 8
#define PP 32
#define DD 512
#define HH 16
#define QKD 32
#define AA 34
#define INV_NORM (1.0f/300.0f)
#define K3 1536
#define K2 1024

__device__ __forceinline__ uint32_t smem_u32(const void* p) {
    uint32_t a;
    asm("{ .reg .u64 t; cvta.to.shared.u64 t, %1; cvt.u32.u64 %0, t; }" : "=r"(a) : "l"(p));
    return a;
}

// ================= scratch =================
__device__ __align__(1024) __half g_X1h[(size_t)BB*PP*K2];        // [stage|wafer]
__device__ __align__(1024) __half g_acth[(size_t)BB*AA*K2];       // [pm_emb|wafer]
__device__ __align__(1024) __half g_Wpmh[(size_t)DD*K2];
__device__ __align__(1024) __half g_Wkvsh[(size_t)3*DD*K2];
__device__ __align__(128) float g_u[DD];                          // Wpm[:,1024:] @ Wdyn[:,0]
__device__ __align__(128) float g_v[3*DD];                        // Wkvs[:,1024:] @ Wtime
__device__ __align__(128) float g_remain[BB*PP];
__device__ __align__(128) float g_dur[BB*AA];
__device__ __align__(128) float g_pm_emb[(size_t)BB*PP*DD];
__device__ __align__(128) float g_KVS[(size_t)BB*AA*3*DD];
__device__ __align__(128) float g_g12[(size_t)BB*2*DD];
__device__ __align__(128) float g_pmmean[(size_t)BB*DD];
__device__ __align__(128) float g_pmrb[(size_t)BB*DD];
__device__ __align__(128) float g_ctx[(size_t)BB*3*DD];
__device__ __align__(128) float g_h1[(size_t)BB*DD];
__device__ __align__(128) float g_ctxt[(size_t)BB*DD];
__device__ __align__(128) float g_q[(size_t)BB*DD];
__device__ __align__(128) float g_attout[(size_t)BB*DD];
__device__ __align__(128) float g_mh[(size_t)BB*DD];
__device__ __align__(128) float g_dll[BB];
__device__ __align__(128) float g_dpm[BB*PP];
__device__ int g_mask_wordmode;

__device__ __forceinline__ bool mask_at(const void* m, int i)
{
    if (g_mask_wordmode) return ((const unsigned int*)m)[i] != 0u;
    return ((const unsigned char*)m)[i] != 0u;
}

// ================= merged builder: x1 + g12 + mask-detect =================
__global__ void build_all(const float* __restrict__ enc_row, const float* __restrict__ enc_col,
                          const float* __restrict__ clockv, const float* __restrict__ endt,
                          const int* __restrict__ loc_id, const int* __restrict__ robot,
                          const int* __restrict__ hold, const int* __restrict__ stage,
                          const int* __restrict__ ll1, const int* __restrict__ ll2,
                          const unsigned int* __restrict__ mw)
{
    int blk = blockIdx.x;
    if (blk < BB * PP) {
        int b = blk >> 5, p = blk & 31;
        float ck = clockv[b];
        float et = endt[b * PP + p];
        float remain = fmaxf(et - ck, 0.f) * INV_NORM;
        int st = stage[b * PP + p] - 1;
        int hw = hold[b * PP + p];
        __half* row = g_X1h + (size_t)blk * K2;
        const float* cs = enc_col + ((size_t)b * NS_ + st) * DD;
        const float* ws = (hw >= 0) ? enc_row + ((size_t)b * NW_ + hw) * DD : nullptr;
        for (int d = threadIdx.x; d < DD; d += blockDim.x) {
            row[d] = __float2half_rn(cs[d]);
            row[DD + d] = __float2half_rn(ws ? ws[d] : 0.f);
        }
        if (threadIdx.x == 0) {
            g_remain[blk] = remain;
            int rb = robot[b];
            float pk = ck + 3.f * (loc_id[b * PP + p] != rb);
            g_dpm[blk] = (fmaxf(et, pk) + 9.f - ck) * INV_NORM;
            if (p == 0) g_dll[b] = (3.f * (rb != 0) + 9.f) * INV_NORM;
        }
    } else if (blk < BB * PP + BB) {
        int b = blk - BB * PP;
        const float* r1 = enc_row + ((size_t)b * NW_ + ll1[b]) * DD;
        const float* r2 = enc_row + ((size_t)b * NW_ + ll2[b]) * DD;
        float* dst = g_g12 + (size_t)b * 2 * DD;
        for (int d = threadIdx.x; d < DD; d += blockDim.x) {
            dst[d] = r1[d];
            dst[DD + d] = r2[d];
        }
    } else {
        __shared__ int bad;
        if (threadIdx.x == 0) bad = 0;
        __syncthreads();
        for (int i = threadIdx.x; i < (BB * AA) / 4; i += blockDim.x) {
            unsigned int w = mw[i];
            if (w != 0u && w != 1u && w != 0x3F800000u) atomicExch(&bad, 1);
        }
        __syncthreads();
        if (threadIdx.x == 0) g_mask_wordmode = !bad;
    }
}

// ================= weight prep: first-1024-col fp16 convert =================
__global__ void wconv_all(const float* __restrict__ Wpm, const float* __restrict__ Wk,
                          const float* __restrict__ Wv, const float* __restrict__ Wshk)
{
    const int n = DD * K2;
    int idx = blockIdx.x * blockDim.x + threadIdx.x;
    if (idx >= 4 * n) return;
    int which = idx / n, off = idx - which * n;
    int r = off >> 10, c = off & (K2 - 1);
    const float* src = (which == 0) ? Wpm : (which == 1) ? Wk : (which == 2) ? Wv : Wshk;
    __half* dst = (which == 0) ? g_Wpmh : g_Wkvsh + (size_t)(which - 1) * n;
    dst[off] = __float2half_rn(src[(size_t)r * K3 + c]);
}

// rank-1 vectors: u[n] = Wpm[n,1024:]·Wdyn[:,0]; v[n] = Wkvs[n,1024:]·Wtime
__global__ void matvec_uv(const float* __restrict__ Wpm, const float* __restrict__ Wk,
                          const float* __restrict__ Wv, const float* __restrict__ Wshk,
                          const float* __restrict__ Wdyn, const float* __restrict__ Wtime)
{
    int gw = blockIdx.x * (blockDim.x >> 5) + (threadIdx.x >> 5);
    int lane = threadIdx.x & 31;
    if (gw >= 4 * DD) return;
    float s = 0.f;
    if (gw < DD) {
        const float* wrow = Wpm + (size_t)gw * K3 + K2;
        for (int d = lane; d < DD; d += 32) s += wrow[d] * Wdyn[2 * d];
    } else {
        int nn = gw - DD;
        const float* W = (nn < DD) ? Wk : (nn < 2 * DD) ? Wv : Wshk;
        const float* wrow = W + (size_t)(nn % DD) * K3 + K2;
        for (int d = lane; d < DD; d += 32) s += wrow[d] * Wtime[d];
    }
    #pragma unroll
    for (int o = 16; o > 0; o >>= 1) s += __shfl_xor_sync(0xffffffffu, s, o);
    if (lane == 0) {
        if (gw < DD) g_u[gw] = s;
        else g_v[gw - DD] = s;
    }
}

// ================= fp16 NT GEMM via mma.sync, rank-1 epilogue =================
__global__ void __launch_bounds__(256) gemm_mma(
    const __half* __restrict__ A, const __half* __restrict__ Bm,
    float* __restrict__ C, int M, int K, int ldc,
    const float* __restrict__ coef, const float* __restrict__ rv)
{
    extern __shared__ char smem[];
    const uint32_t sb = smem_u32(smem);
    const int tid = threadIdx.x;
    const int lane = tid & 31;
    const int wid = tid >> 5;
    const int wm = wid >> 2;
    const int wn = wid & 3;
    const int bm = blockIdx.y * 128;
    const int bn = blockIdx.x * 128;
    const uint32_t STAGE = 32768;
    const int CH = K / 64;

    float acc[4][4][4];
    #pragma unroll
    for (int i = 0; i < 4; i++)
        #pragma unroll
        for (int j = 0; j < 4; j++)
            #pragma unroll
            for (int r = 0; r < 4; r++) acc[i][j][r] = 0.f;

    auto load_tiles = [&](int st, int kk) {
        uint32_t ab = sb + st * STAGE;
        uint32_t bb = ab + 16384;
        #pragma unroll
        for (int i = 0; i < 4; i++) {
            int idx = tid + i * 256;
            int row = idx >> 3, ch = idx & 7;
            uint32_t sw = (uint32_t)(row * 128 + ((ch ^ (row & 7)) << 4));
            const __half* ag = A  + (size_t)(bm + row) * K + kk * 64 + ch * 8;
            const __half* bg = Bm + (size_t)(bn + row) * K + kk * 64 + ch * 8;
            asm volatile("cp.async.cg.shared.global [%0], [%1], 16;" :: "r"(ab + sw), "l"(ag));
            asm volatile("cp.async.cg.shared.global [%0], [%1], 16;" :: "r"(bb + sw), "l"(bg));
        }
    };

    load_tiles(0, 0);
    asm volatile("cp.async.commit_group;");

    for (int it = 0; it < CH; ++it) {
        int st = it & 1;
        if (it + 1 < CH) {
            load_tiles((it + 1) & 1, it + 1);
            asm volatile("cp.async.commit_group;");
            asm volatile("cp.async.wait_group 1;");
        } else {
            asm volatile("cp.async.wait_group 0;");
        }
        __syncthreads();

        uint32_t aB = sb + st * STAGE;
        uint32_t bB = aB + 16384;
        #pragma unroll
        for (int kk8 = 0; kk8 < 8; kk8 += 2) {
            uint32_t ar[4][4], br[4][2];
            #pragma unroll
            for (int mf = 0; mf < 4; mf++) {
                int row = wm * 64 + mf * 16 + (lane & 15);
                int c = kk8 + (lane >> 4);
                uint32_t ad = aB + row * 128 + ((c ^ (row & 7)) << 4);
                asm volatile("ldmatrix.sync.aligned.m8n8.x4.shared.b16 {%0,%1,%2,%3}, [%4];"
                    : "=r"(ar[mf][0]), "=r"(ar[mf][1]), "=r"(ar[mf][2]), "=r"(ar[mf][3]) : "r"(ad));
            }
            #pragma unroll
            for (int nfp = 0; nfp < 2; nfp++) {
                int nr = wn * 32 + nfp * 16 + ((lane & 7) | ((lane >> 4) << 3));
                int c = kk8 + ((lane >> 3) & 1);
                uint32_t bd = bB + nr * 128 + ((c ^ (nr & 7)) << 4);
                asm volatile("ldmatrix.sync.aligned.m8n8.x4.shared.b16 {%0,%1,%2,%3}, [%4];"
                    : "=r"(br[2 * nfp][0]), "=r"(br[2 * nfp][1]),
                      "=r"(br[2 * nfp + 1][0]), "=r"(br[2 * nfp + 1][1]) : "r"(bd));
            }
            #pragma unroll
            for (int mf = 0; mf < 4; mf++)
                #pragma unroll
                for (int nf = 0; nf < 4; nf++) {
                    asm volatile(
                        "mma.sync.aligned.m16n8k16.row.col.f32.f16.f16.f32 "
                        "{%0,%1,%2,%3}, {%4,%5,%6,%7}, {%8,%9}, {%0,%1,%2,%3};"
                        : "+f"(acc[mf][nf][0]), "+f"(acc[mf][nf][1]),
                          "+f"(acc[mf][nf][2]), "+f"(acc[mf][nf][3])
                        : "r"(ar[mf][0]), "r"(ar[mf][1]), "r"(ar[mf][2]), "r"(ar[mf][3]),
                          "r"(br[nf][0]), "r"(br[nf][1]));
                }
        }
        __syncthreads();
    }

    #pragma unroll
    for (int mf = 0; mf < 4; mf++) {
        int r0 = bm + wm * 64 + mf * 16 + (lane >> 2);
        float cf0 = coef[r0], cf1 = coef[r0 + 8];
        #pragma unroll
        for (int nf = 0; nf < 4; nf++) {
            int c0 = bn + wn * 32 + nf * 8 + (lane & 3) * 2;
            float v0 = rv[c0], v1 = rv[c0 + 1];
            float* p0 = C + (size_t)r0 * ldc + c0;
            float* p1 = C + (size_t)(r0 + 8) * ldc + c0;
            p0[0] = acc[mf][nf][0] + cf0 * v0;
            p0[1] = acc[mf][nf][1] + cf0 * v1;
            p1[0] = acc[mf][nf][2] + cf1 * v0;
            p1[1] = acc[mf][nf][3] + cf1 * v1;
        }
    }
}

// ================= fp32 NT SGEMM 64x64 =================
template<bool RELU>
__device__ __forceinline__ void sgemm64_body(
    const float* __restrict__ A, const float* __restrict__ Bm,
    float* __restrict__ C, int K, int ldc, int n0, const float* __restrict__ bias,
    int bm, int bn)
{
    __shared__ float As[16][64];
    __shared__ float Bs[16][64];
    const int tid = threadIdx.x;
    const int tx = tid & 15;
    const int ty = tid >> 4;
    const int lr = tid >> 2;
    const int lc = (tid & 3) * 4;

    float acc[4][4];
    #pragma unroll
    for (int i = 0; i < 4; i++)
        #pragma unroll
        for (int j = 0; j < 4; j++) acc[i][j] = 0.f;

    const float* Aptr = A + (size_t)(bm + lr) * K + lc;
    const float* Bptr = Bm + (size_t)(bn + lr) * K + lc;

    for (int k0 = 0; k0 < K; k0 += 16) {
        float4 av = *(const float4*)(Aptr + k0);
        float4 bv = *(const float4*)(Bptr + k0);
        __syncthreads();
        As[lc + 0][lr] = av.x; As[lc + 1][lr] = av.y;
        As[lc + 2][lr] = av.z; As[lc + 3][lr] = av.w;
        Bs[lc + 0][lr] = bv.x; Bs[lc + 1][lr] = bv.y;
        Bs[lc + 2][lr] = bv.z; Bs[lc + 3][lr] = bv.w;
        __syncthreads();
        #pragma unroll
        for (int kk = 0; kk < 16; kk++) {
            float a[4], b[4];
            *(float4*)a = *(const float4*)&As[kk][ty * 4];
            *(float4*)b = *(const float4*)&Bs[kk][tx * 4];
            #pragma unroll
            for (int i = 0; i < 4; i++)
                #pragma unroll
                for (int j = 0; j < 4; j++)
                    acc[i][j] = fmaf(a[i], b[j], acc[i][j]);
        }
    }
    #pragma unroll
    for (int i = 0; i < 4; i++) {
        int row = bm + ty * 4 + i;
        #pragma unroll
        for (int j = 0; j < 4; j++) {
            int col = bn + tx * 4 + j;
            float v = acc[i][j];
            if (bias) v += bias[col];
            if (RELU) v = fmaxf(v, 0.f);
            C[(size_t)row * ldc + n0 + col] = v;
        }
    }
}

template<bool RELU>
__global__ void __launch_bounds__(256) sgemm64(
    const float* __restrict__ A, const float* __restrict__ Bm,
    float* __restrict__ C, int K, int ldc, int n0, const float* __restrict__ bias)
{
    sgemm64_body<RELU>(A, Bm, C, K, ldc, n0, bias, blockIdx.y * 64, blockIdx.x * 64);
}

__global__ void __launch_bounds__(256) ctx3_gemm(
    const float* __restrict__ W0, const float* __restrict__ W1, const float* __restrict__ W2)
{
    int z = blockIdx.z;
    const float* A = (z == 0) ? g_g12 : (z == 1) ? g_pmmean : g_pmrb;
    const float* W = (z == 0) ? W0 : (z == 1) ? W1 : W2;
    int K = (z == 0) ? 2 * DD : DD;
    sgemm64_body<false>(A, W, g_ctx, K, 3 * DD, z * DD, nullptr,
                        blockIdx.y * 64, blockIdx.x * 64);
}

// ================= action builder (K=1024 layout) =================
__global__ void build_actionh(const float* __restrict__ enc_row,
                              const int* __restrict__ ll1, const int* __restrict__ ll2,
                              const int* __restrict__ hold)
{
    int blk = blockIdx.x;
    int b = blk / AA, j = blk - b * AA;
    __half* row = g_acth + (size_t)blk * K2;
    if (j < 2) {
        int rec = (j == 0) ? ll1[b] : ll2[b];
        const float* g = enc_row + ((size_t)b * NW_ + rec) * DD;
        for (int d = threadIdx.x; d < DD; d += blockDim.x) {
            row[d] = __float2half_rn(0.f);
            row[DD + d] = __float2half_rn(g[d]);
        }
        if (threadIdx.x == 0) g_dur[blk] = g_dll[b];
    } else {
        int p = j - 2;
        int hw = hold[b * PP + p];
        const float* ws = (hw >= 0) ? enc_row + ((size_t)b * NW_ + hw) * DD : nullptr;
        const float* pe = g_pm_emb + (size_t)(b * PP + p) * DD;
        for (int d = threadIdx.x; d < DD; d += blockDim.x) {
            row[d] = __float2half_rn(pe[d]);
            row[DD + d] = __float2half_rn(ws ? ws[d] : 0.f);
        }
        if (threadIdx.x == 0) g_dur[blk] = g_dpm[b * PP + p];
    }
}

__global__ void pm_mean_rb(const int* __restrict__ robot)
{
    int b = blockIdx.x;
    int rb = robot[b];
    for (int d = threadIdx.x; d < DD; d += blockDim.x) {
        float s = 0.f;
        #pragma unroll 8
        for (int p = 0; p < PP; p++)
            s += g_pm_emb[((size_t)(b * PP + p)) * DD + d];
        g_pmmean[(size_t)b * DD + d] = s * (1.f / PP);
        g_pmrb[(size_t)b * DD + d] = g_pm_emb[((size_t)(b * PP + rb)) * DD + d];
    }
}

// ================= attention =================
__global__ void attention(const void* __restrict__ mask)
{
    int b = blockIdx.x;
    int h = threadIdx.x >> 5, lane = threadIdx.x & 31;
    __shared__ float ps[HH][AA + 2];
    float q = g_q[(size_t)b * DD + h * QKD + lane];
    const float scale = rsqrtf((float)QKD);
    for (int j = 0; j < AA; j++) {
        float kv = g_KVS[((size_t)(b * AA + j)) * (3 * DD) + h * QKD + lane];
        float s = q * kv;
        #pragma unroll
        for (int o = 16; o > 0; o >>= 1) s += __shfl_xor_sync(0xffffffffu, s, o);
        if (lane == 0) ps[h][j] = s * scale + (mask_at(mask, b * AA + j) ? 0.f : -1e10f);
    }
    __syncwarp();
    float m = -INFINITY;
    for (int j = 0; j < AA; j++) m = fmaxf(m, ps[h][j]);
    float sum = 0.f;
    for (int j = 0; j < AA; j++) sum += expf(ps[h][j] - m);
    float inv = 1.f / sum;
    float o = 0.f;
    for (int j = 0; j < AA; j++)
        o += expf(ps[h][j] - m) * inv * g_KVS[((size_t)(b * AA + j)) * (3 * DD) + DD + h * QKD + lane];
    g_attout[(size_t)b * DD + h * QKD + lane] = o;
}

__global__ void final_kernel(const void* __restrict__ mask, float* __restrict__ out)
{
    int b = blockIdx.x;
    int w = threadIdx.x >> 5, lane = threadIdx.x & 31;
    __shared__ float sc[AA];
    const float* mh = g_mh + (size_t)b * DD;
    const float scale = rsqrtf((float)DD);
    for (int a = w; a < AA; a += 8) {
        const float* s = g_KVS + ((size_t)(b * AA + a)) * (3 * DD) + 2 * DD;
        float acc = 0.f;
        for (int d = lane; d < DD; d += 32) acc = fmaf(mh[d], s[d], acc);
        #pragma unroll
        for (int o = 16; o > 0; o >>= 1) acc += __shfl_xor_sync(0xffffffffu, acc, o);
        if (lane == 0)
            sc[a] = 10.f * tanhf(acc * scale) + (mask_at(mask, b * AA + a) ? 0.f : -1e10f);
    }
    __syncthreads();
    if (threadIdx.x < AA) {
        float m = -INFINITY;
        for (int j = 0; j < AA; j++) m = fmaxf(m, sc[j]);
        float sum = 0.f;
        for (int j = 0; j < AA; j++) sum += expf(sc[j] - m);
        out[b * AA + threadIdx.x] = expf(sc[threadIdx.x] - m) / sum;
    }
}

// ================= launch =================
extern "C" void kernel_launch(void* const* d_in, const int* in_sizes, int n_in,
                              void* d_out, int out_size)
{
    const float* enc_row = (const float*)d_in[0];
    const float* enc_col = (const float*)d_in[1];
    const float* clockv  = (const float*)d_in[2];
    const float* endt    = (const float*)d_in[3];
    const int* loc_id    = (const int*)d_in[4];
    const int* robot     = (const int*)d_in[5];
    const int* hold      = (const int*)d_in[6];
    const int* stage     = (const int*)d_in[7];
    const int* ll1       = (const int*)d_in[8];
    const int* ll2       = (const int*)d_in[9];
    const void* mask     = d_in[10];
    const float* W_dyn   = (const float*)d_in[11];
    const float* W_pmcat = (const float*)d_in[12];
    const float* W_time  = (const float*)d_in[13];
    const float* W_llctx = (const float*)d_in[14];
    const float* W_pmctx = (const float*)d_in[15];
    const float* W_rbctx = (const float*)d_in[16];
    const float* W_cc1   = (const float*)d_in[17];
    const float* b_cc1   = (const float*)d_in[18];
    const float* W_cc2   = (const float*)d_in[19];
    const float* b_cc2   = (const float*)d_in[20];
    const float* Wq      = (const float*)d_in[21];
    const float* Wk      = (const float*)d_in[22];
    const float* Wv      = (const float*)d_in[23];
    const float* Wshk    = (const float*)d_in[24];
    const float* W_mhc   = (const float*)d_in[25];
    const float* b_mhc   = (const float*)d_in[26];
    float* out = (float*)d_out;

    __half *X1h, *acth, *Wpmh, *Wkvsh;
    float *pm_emb, *KVS, *ctx, *h1, *ctxt, *qm, *attout, *mh, *remain, *dur, *uu, *vv;
    cudaGetSymbolAddress((void**)&X1h, g_X1h);
    cudaGetSymbolAddress((void**)&acth, g_acth);
    cudaGetSymbolAddress((void**)&Wpmh, g_Wpmh);
    cudaGetSymbolAddress((void**)&Wkvsh, g_Wkvsh);
    cudaGetSymbolAddress((void**)&pm_emb, g_pm_emb);
    cudaGetSymbolAddress((void**)&KVS, g_KVS);
    cudaGetSymbolAddress((void**)&ctx, g_ctx);
    cudaGetSymbolAddress((void**)&h1, g_h1);
    cudaGetSymbolAddress((void**)&ctxt, g_ctxt);
    cudaGetSymbolAddress((void**)&qm, g_q);
    cudaGetSymbolAddress((void**)&attout, g_attout);
    cudaGetSymbolAddress((void**)&mh, g_mh);
    cudaGetSymbolAddress((void**)&remain, g_remain);
    cudaGetSymbolAddress((void**)&dur, g_dur);
    cudaGetSymbolAddress((void**)&uu, g_u);
    cudaGetSymbolAddress((void**)&vv, g_v);

    static cudaStream_t s1 = nullptr;
    static cudaEvent_t eF = nullptr, eW = nullptr, eA = nullptr, eB = nullptr;
    if (!s1) {
        cudaStreamCreateWithFlags(&s1, cudaStreamNonBlocking);
        cudaEventCreateWithFlags(&eF, cudaEventDisableTiming);
        cudaEventCreateWithFlags(&eW, cudaEventDisableTiming);
        cudaEventCreateWithFlags(&eA, cudaEventDisableTiming);
        cudaEventCreateWithFlags(&eB, cudaEventDisableTiming);
    }

    const int MMA_SMEM = 65536;
    cudaFuncSetAttribute(gemm_mma, cudaFuncAttributeMaxDynamicSharedMemorySize, MMA_SMEM);

    // --- fork s1 from the captured origin stream (legal capture fork) ---
    cudaEventRecord(eF, 0);
    cudaStreamWaitEvent(s1, eF, 0);

    // --- stream 1: weight prep (overlaps build_all) ---
    wconv_all<<<(4 * DD * K2 + 255) / 256, 256, 0, s1>>>(W_pmcat, Wk, Wv, Wshk);
    matvec_uv<<<(4 * DD) / 8, 256, 0, s1>>>(W_pmcat, Wk, Wv, Wshk, W_dyn, W_time);
    cudaEventRecord(eW, s1);

    // --- stream 0: builders -> GEMM1 ---
    build_all<<<BB * PP + BB + 1, 128>>>(enc_row, enc_col, clockv, endt, loc_id, robot,
                                         hold, stage, ll1, ll2, (const unsigned int*)mask);
    cudaStreamWaitEvent(0, eW, 0);
    gemm_mma<<<dim3(DD / 128, BB * PP / 128), 256, MMA_SMEM>>>(X1h, Wpmh, pm_emb,
                                                               BB * PP, K2, DD, remain, uu);
    cudaEventRecord(eA, 0);

    // --- stream 1 (branch B): pm_mean -> ctx -> cc1 -> cc2 -> q ---
    cudaStreamWaitEvent(s1, eA, 0);
    pm_mean_rb<<<BB, 256, 0, s1>>>(robot);
    ctx3_gemm<<<dim3(DD / 64, BB / 64, 3), 256, 0, s1>>>(W_llctx, W_pmctx, W_rbctx);
    sgemm64<true><<<dim3(DD / 64, BB / 64), 256, 0, s1>>>(ctx, W_cc1, h1, 3 * DD, DD, 0, b_cc1);
    sgemm64<false><<<dim3(DD / 64, BB / 64), 256, 0, s1>>>(h1, W_cc2, ctxt, DD, DD, 0, b_cc2);
    sgemm64<false><<<dim3(DD / 64, BB / 64), 256, 0, s1>>>(ctxt, Wq, qm, DD, DD, 0, nullptr);
    cudaEventRecord(eB, s1);

    // --- stream 0 (branch A): action -> KVS GEMM ---
    build_actionh<<<BB * AA, 128>>>(enc_row, ll1, ll2, hold);
    gemm_mma<<<dim3(3 * DD / 128, BB * AA / 128), 256, MMA_SMEM>>>(acth, Wkvsh, KVS,
                                                                   BB * AA, K2, 3 * DD, dur, vv);

    // --- join, tail ---
    cudaStreamWaitEvent(0, eB, 0);
    attention<<<BB, HH * 32>>>(mask);
    sgemm64<false><<<dim3(DD / 64, BB / 64), 256>>>(attout, W_mhc, mh, DD, DD, 0, b_mhc);
    final_kernel<<<BB, 256>>>(mask, out);
}